// round 3
// baseline (speedup 1.0000x reference)
#include <cuda_runtime.h>
#include <math.h>

#define E_DIM 1024
#define M_DIM 4096
#define H_NUM 16
#define HD 64
#define B_SZ 4
#define SPITCH 68

// Scratch (allocation-free rule: __device__ globals)
__device__ float g_q [M_DIM * E_DIM];
__device__ float g_k1[M_DIM * E_DIM];
__device__ float g_k2[M_DIM * E_DIM];
__device__ float g_v [M_DIM * E_DIM];
__device__ float g_ao[M_DIM * E_DIM];

// ---------------------------------------------------------------------------
// 128x128x8 fp32 GEMM body: C[M,N] = A[M,K] @ W[N,K]^T + bias[N]
// M=4096 (per blockIdx.y*128), N=1024, K=1024. 256 threads, 8x8 per thread.
// ---------------------------------------------------------------------------
__device__ __forceinline__ void gemm128(const float* __restrict__ A,
                                        const float* __restrict__ W,
                                        const float* __restrict__ bias,
                                        float* __restrict__ C) {
    __shared__ float As[8][132];
    __shared__ float Bs[8][132];

    const int tid = threadIdx.x;
    const int tx = tid & 15;
    const int ty = tid >> 4;
    const int bm = blockIdx.y * 128;
    const int bn = blockIdx.x * 128;

    const int lr = tid >> 1;          // 0..127 row within tile
    const int lc = (tid & 1) * 4;     // 0 or 4 (k offset)

    const float* Ap = A + (size_t)(bm + lr) * E_DIM + lc;
    const float* Wp = W + (size_t)(bn + lr) * E_DIM + lc;

    float acc[8][8];
#pragma unroll
    for (int i = 0; i < 8; i++)
#pragma unroll
        for (int j = 0; j < 8; j++) acc[i][j] = 0.0f;

    for (int kb = 0; kb < E_DIM; kb += 8) {
        float4 a4 = *(const float4*)(Ap + kb);
        float4 b4 = *(const float4*)(Wp + kb);
        __syncthreads();
        As[lc + 0][lr] = a4.x; As[lc + 1][lr] = a4.y;
        As[lc + 2][lr] = a4.z; As[lc + 3][lr] = a4.w;
        Bs[lc + 0][lr] = b4.x; Bs[lc + 1][lr] = b4.y;
        Bs[lc + 2][lr] = b4.z; Bs[lc + 3][lr] = b4.w;
        __syncthreads();
#pragma unroll
        for (int kk = 0; kk < 8; kk++) {
            float4 a0 = *(const float4*)&As[kk][ty * 4];
            float4 a1 = *(const float4*)&As[kk][64 + ty * 4];
            float4 b0 = *(const float4*)&Bs[kk][tx * 4];
            float4 b1 = *(const float4*)&Bs[kk][64 + tx * 4];
            float ra[8] = {a0.x, a0.y, a0.z, a0.w, a1.x, a1.y, a1.z, a1.w};
            float rb[8] = {b0.x, b0.y, b0.z, b0.w, b1.x, b1.y, b1.z, b1.w};
#pragma unroll
            for (int i = 0; i < 8; i++)
#pragma unroll
                for (int j = 0; j < 8; j++)
                    acc[i][j] += ra[i] * rb[j];
        }
    }

#pragma unroll
    for (int i = 0; i < 8; i++) {
        int row = bm + ((i < 4) ? (ty * 4 + i) : (64 + ty * 4 + (i - 4)));
#pragma unroll
        for (int jh = 0; jh < 2; jh++) {
            int col = bn + jh * 64 + tx * 4;
            float4 o;
            o.x = acc[i][jh * 4 + 0] + bias[col + 0];
            o.y = acc[i][jh * 4 + 1] + bias[col + 1];
            o.z = acc[i][jh * 4 + 2] + bias[col + 2];
            o.w = acc[i][jh * 4 + 3] + bias[col + 3];
            *(float4*)&C[(size_t)row * E_DIM + col] = o;
        }
    }
}

// Fused 4-way projection: z=0:q z=1:k1 z=2:k2 z=3:v
extern "C" __global__ void __launch_bounds__(256)
proj_kernel(const float* __restrict__ query, const float* __restrict__ key,
            const float* __restrict__ value, const float* __restrict__ wq,
            const float* __restrict__ wk1, const float* __restrict__ wk2,
            const float* __restrict__ wv, const float* __restrict__ bias) {
    const float* A;
    const float* W;
    float* C;
    int z = blockIdx.z;
    if (z == 0)      { A = query; W = wq;  C = g_q;  }
    else if (z == 1) { A = key;   W = wk1; C = g_k1; }
    else if (z == 2) { A = key;   W = wk2; C = g_k2; }
    else             { A = value; W = wv;  C = g_v;  }
    gemm128(A, W, bias + z * E_DIM, C);
}

extern "C" __global__ void __launch_bounds__(256)
out_kernel(const float* __restrict__ W, const float* __restrict__ bias,
           float* __restrict__ C) {
    gemm128(g_ao, W, bias, C);
}

// ---------------------------------------------------------------------------
// Gaussian-kernel attention. Block = (head bh, 64-row q tile). 256 threads.
// smem: sq, sk1, sk2, sv, sw (64x68 each) + q2s/k1n/k2n (64 each)
// ---------------------------------------------------------------------------
#define ATTN_SMEM ((5 * 64 * SPITCH + 3 * 64) * 4)

extern "C" __global__ void __launch_bounds__(256)
attn_kernel(const float* __restrict__ pi) {
    extern __shared__ float sm[];
    float* sq  = sm;
    float* sk1 = sq  + 64 * SPITCH;
    float* sk2 = sk1 + 64 * SPITCH;
    float* sv  = sk2 + 64 * SPITCH;
    float* sw  = sv  + 64 * SPITCH;
    float* q2s = sw  + 64 * SPITCH;
    float* k1n = q2s + 64;
    float* k2n = k1n + 64;

    const int tid = threadIdx.x;
    const int tx = tid & 15;
    const int ty = tid >> 4;
    const int qt = blockIdx.x;     // q tile 0..15
    const int bh = blockIdx.y;     // 0..63
    const int b = bh >> 4;
    const int h = bh & 15;
    const int q0 = qt * 64;
    const size_t colbase = (size_t)h * HD;

    float p1 = fminf(fmaxf(fabsf(pi[h]), 1e-6f), 2.0f);
    float p2 = fminf(fmaxf(fabsf(pi[H_NUM + h]), 1e-6f), 2.0f);

    // load q tile (64x64), natural layout
#pragma unroll
    for (int i = 0; i < 4; i++) {
        int lin = i * 256 + tid;
        int r = lin >> 4;
        int c = (lin & 15) * 4;
        const float* src = g_q + ((size_t)(q0 + r) * B_SZ + b) * E_DIM + colbase + c;
        *(float4*)&sq[r * SPITCH + c] = *(const float4*)src;
    }
    __syncthreads();
    if (tid < 64) {
        float s = 0.0f;
#pragma unroll
        for (int d = 0; d < 64; d += 4) {
            float4 v4 = *(const float4*)&sq[tid * SPITCH + d];
            s += v4.x * v4.x + v4.y * v4.y + v4.z * v4.z + v4.w * v4.w;
        }
        q2s[tid] = s;
    }

    float accO[4][4] = {};
    float den[4] = {0.0f, 0.0f, 0.0f, 0.0f};

    for (int st = 0; st < 16; st++) {
        const int s0 = st * 64;
        __syncthreads();   // previous AV reads done before overwrite
#pragma unroll
        for (int i = 0; i < 4; i++) {
            int lin = i * 256 + tid;
            int r = lin >> 4;
            int c = (lin & 15) * 4;
            size_t goff = ((size_t)(s0 + r) * B_SZ + b) * E_DIM + colbase + c;
            *(float4*)&sk1[r * SPITCH + c] = *(const float4*)(g_k1 + goff);
            *(float4*)&sk2[r * SPITCH + c] = *(const float4*)(g_k2 + goff);
            *(float4*)&sv [r * SPITCH + c] = *(const float4*)(g_v  + goff);
        }
        __syncthreads();
        if (tid < 128) {
            const float* krow = ((tid < 64) ? sk1 : sk2) + (tid & 63) * SPITCH;
            float s = 0.0f;
#pragma unroll
            for (int d = 0; d < 64; d += 4) {
                float4 v4 = *(const float4*)&krow[d];
                s += v4.x * v4.x + v4.y * v4.y + v4.z * v4.z + v4.w * v4.w;
            }
            ((tid < 64) ? k1n : k2n)[tid & 63] = s;
        }
        __syncthreads();

        // scores: a1 = q.k1, a2 = q.k2 for this 64x64 tile (4x4 per thread)
        float a1[4][4] = {}, a2[4][4] = {};
#pragma unroll
        for (int d = 0; d < 64; d += 4) {
            float4 qa[4];
#pragma unroll
            for (int i = 0; i < 4; i++)
                qa[i] = *(const float4*)&sq[(ty * 4 + i) * SPITCH + d];
#pragma unroll
            for (int j = 0; j < 4; j++) {
                float4 ka = *(const float4*)&sk1[(tx * 4 + j) * SPITCH + d];
                float4 kb = *(const float4*)&sk2[(tx * 4 + j) * SPITCH + d];
#pragma unroll
                for (int i = 0; i < 4; i++) {
                    a1[i][j] += qa[i].x * ka.x + qa[i].y * ka.y
                              + qa[i].z * ka.z + qa[i].w * ka.w;
                    a2[i][j] += qa[i].x * kb.x + qa[i].y * kb.y
                              + qa[i].z * kb.z + qa[i].w * kb.w;
                }
            }
        }

        // weights w = p1*exp(-c1*d1) + p2*exp(-c2*d2)
#pragma unroll
        for (int i = 0; i < 4; i++) {
            float q2v = q2s[ty * 4 + i];
            float wv_[4];
#pragma unroll
            for (int j = 0; j < 4; j++) {
                int s_ = tx * 4 + j;
                float d1 = q2v + k1n[s_] - 2.0f * a1[i][j];
                float d2 = q2v + k2n[s_] - 2.0f * a2[i][j];
                float w = p1 * __expf(-0.0625f * d1) + p2 * __expf(-0.1875f * d2);
                den[i] += w;
                wv_[j] = w;
            }
            *(float4*)&sw[(ty * 4 + i) * SPITCH + tx * 4] =
                make_float4(wv_[0], wv_[1], wv_[2], wv_[3]);
        }
        __syncthreads();

        // AV: accO[t][d] += w[t][s] * v[s][d]
#pragma unroll 4
        for (int s_ = 0; s_ < 64; s_++) {
            float4 v4 = *(const float4*)&sv[s_ * SPITCH + tx * 4];
#pragma unroll
            for (int i = 0; i < 4; i++) {
                float w = sw[(ty * 4 + i) * SPITCH + s_];
                accO[i][0] += w * v4.x;
                accO[i][1] += w * v4.y;
                accO[i][2] += w * v4.z;
                accO[i][3] += w * v4.w;
            }
        }
    }

    // reduce den across tx lanes (lane bits 0..3)
#pragma unroll
    for (int i = 0; i < 4; i++) {
#pragma unroll
        for (int m = 1; m < 16; m <<= 1)
            den[i] += __shfl_xor_sync(0xffffffffu, den[i], m);
    }

#pragma unroll
    for (int i = 0; i < 4; i++) {
        float inv = 1.0f / (den[i] + 1e-6f);
        int t = q0 + ty * 4 + i;
        float4 o = make_float4(accO[i][0] * inv, accO[i][1] * inv,
                               accO[i][2] * inv, accO[i][3] * inv);
        *(float4*)&g_ao[((size_t)t * B_SZ + b) * E_DIM + colbase + tx * 4] = o;
    }
}

// ---------------------------------------------------------------------------
extern "C" void kernel_launch(void* const* d_in, const int* in_sizes, int n_in,
                              void* d_out, int out_size) {
    const float* query = (const float*)d_in[0];
    const float* key   = (const float*)d_in[1];
    const float* value = (const float*)d_in[2];
    const float* wq    = (const float*)d_in[3];
    const float* wk1   = (const float*)d_in[4];
    const float* wk2   = (const float*)d_in[5];
    const float* wv    = (const float*)d_in[6];
    const float* bias  = (const float*)d_in[7];
    const float* wo    = (const float*)d_in[8];
    const float* bo    = (const float*)d_in[9];
    const float* pi    = (const float*)d_in[10];
    float* out = (float*)d_out;

    cudaFuncSetAttribute(attn_kernel,
                         cudaFuncAttributeMaxDynamicSharedMemorySize, ATTN_SMEM);

    dim3 gproj(8, 32, 4);
    proj_kernel<<<gproj, 256>>>(query, key, value, wq, wk1, wk2, wv, bias);

    dim3 gattn(16, 64);
    attn_kernel<<<gattn, 256, ATTN_SMEM>>>(pi);

    dim3 gout(8, 32);
    out_kernel<<<gout, 256>>>(wo, bo, out);
}

// round 6
// speedup vs baseline: 1.3378x; 1.3378x over previous
#include <cuda_runtime.h>
#include <cuda_bf16.h>
#include <math.h>
#include <cstdint>

#define E_DIM 1024
#define M_DIM 4096
#define H_NUM 16
#define HD 64
#define B_SZ 4
#define SPITCH 68
#define NELEM (M_DIM * E_DIM)
#define WSZ (E_DIM * E_DIM)

// fp32 scratch
__device__ float g_q [NELEM];
__device__ float g_k1[NELEM];
__device__ float g_k2[NELEM];
__device__ float g_v [NELEM];
__device__ float g_ao[NELEM];

// bf16 hi/lo split buffers
__device__ __nv_bfloat16 in_q_h[NELEM], in_q_l[NELEM];
__device__ __nv_bfloat16 in_k_h[NELEM], in_k_l[NELEM];
__device__ __nv_bfloat16 in_v_h[NELEM], in_v_l[NELEM];
__device__ __nv_bfloat16 ao_h[NELEM],   ao_l[NELEM];
__device__ __nv_bfloat16 w_h[5 * WSZ],  w_l[5 * WSZ];

// ===========================================================================
// helpers
// ===========================================================================
__device__ __forceinline__ uint32_t smem_u32(const void* p) {
    uint32_t a;
    asm("{ .reg .u64 t; cvta.to.shared.u64 t, %1; cvt.u32.u64 %0, t; }"
        : "=r"(a) : "l"(p));
    return a;
}
__device__ __forceinline__ void cp_async16(uint32_t dst, const void* src) {
    asm volatile("cp.async.cg.shared.global [%0], [%1], 16;"
                 :: "r"(dst), "l"(src));
}
__device__ __forceinline__ void cp_commit() {
    asm volatile("cp.async.commit_group;" ::: "memory");
}
__device__ __forceinline__ void cp_wait1() {
    asm volatile("cp.async.wait_group 1;" ::: "memory");
}
__device__ __forceinline__ void cp_wait0() {
    asm volatile("cp.async.wait_group 0;" ::: "memory");
}
__device__ __forceinline__ void ldsm4(uint32_t addr, uint32_t* r) {
    asm volatile("ldmatrix.sync.aligned.m8n8.x4.shared.b16 {%0,%1,%2,%3}, [%4];"
                 : "=r"(r[0]), "=r"(r[1]), "=r"(r[2]), "=r"(r[3]) : "r"(addr));
}
__device__ __forceinline__ void mma16816(float* d, const uint32_t* a,
                                         const uint32_t* b) {
    asm volatile(
        "mma.sync.aligned.m16n8k16.row.col.f32.bf16.bf16.f32 "
        "{%0,%1,%2,%3}, {%4,%5,%6,%7}, {%8,%9}, {%0,%1,%2,%3};"
        : "+f"(d[0]), "+f"(d[1]), "+f"(d[2]), "+f"(d[3])
        : "r"(a[0]), "r"(a[1]), "r"(a[2]), "r"(a[3]), "r"(b[0]), "r"(b[1]));
}

// ===========================================================================
// fp32 -> bf16 hi/lo split
// ===========================================================================
extern "C" __global__ void __launch_bounds__(256)
split_kernel(const float* __restrict__ src, __nv_bfloat16* __restrict__ hi,
             __nv_bfloat16* __restrict__ lo, int n4) {
    int i = blockIdx.x * blockDim.x + threadIdx.x;
    if (i >= n4) return;
    float4 v = ((const float4*)src)[i];
    __nv_bfloat162 h0 = __float22bfloat162_rn(make_float2(v.x, v.y));
    __nv_bfloat162 h1 = __float22bfloat162_rn(make_float2(v.z, v.w));
    float2 f0 = __bfloat1622float2(h0);
    float2 f1 = __bfloat1622float2(h1);
    __nv_bfloat162 l0 = __float22bfloat162_rn(make_float2(v.x - f0.x, v.y - f0.y));
    __nv_bfloat162 l1 = __float22bfloat162_rn(make_float2(v.z - f1.x, v.w - f1.y));
    ((__nv_bfloat162*)hi)[i * 2]     = h0;
    ((__nv_bfloat162*)hi)[i * 2 + 1] = h1;
    ((__nv_bfloat162*)lo)[i * 2]     = l0;
    ((__nv_bfloat162*)lo)[i * 2 + 1] = l1;
}

// ===========================================================================
// mma.sync GEMM: C[M,N] = A[M,K] @ W[N,K]^T + bias  (bf16 hi/lo, fp32 acc)
// CTA 128x128, K chunk 64, 512 threads (16 warps 4x4, 32x32 each).
// smem buffer: Ah | Al | Wh | Wl, 16KB each; double buffered = 128KB.
// ===========================================================================
#define GEMM_SMEM 131072

__device__ __forceinline__ void gemm_mma_body(
    const __nv_bfloat16* __restrict__ Ah, const __nv_bfloat16* __restrict__ Al,
    const __nv_bfloat16* __restrict__ Wh, const __nv_bfloat16* __restrict__ Wl,
    const float* __restrict__ bias, float* __restrict__ C) {
    extern __shared__ char smem[];
    const uint32_t sbase = smem_u32(smem);
    const int tid = threadIdx.x;
    const int lane = tid & 31;
    const int wid = tid >> 5;
    const int bm = blockIdx.y * 128;
    const int bn = blockIdx.x * 128;
    const int wm = (wid & 3) * 32;
    const int wn = (wid >> 2) * 32;

    // loader mapping: 4 threads per row, 2 granules (16B) each, per tile
    const int lrow = tid >> 2;
    const int lc0 = (tid & 3) * 2;
    const size_t goffA = (size_t)(bm + lrow) * E_DIM;
    const size_t goffW = (size_t)(bn + lrow) * E_DIM;

    float acc[2][4][4];
#pragma unroll
    for (int mt = 0; mt < 2; mt++)
#pragma unroll
        for (int nt = 0; nt < 4; nt++)
#pragma unroll
            for (int e = 0; e < 4; e++) acc[mt][nt][e] = 0.0f;

#define LOAD_CHUNK(buf, kc) do {                                              \
    uint32_t dst0 = sbase + (buf) * 65536 + lrow * 128;                       \
    _Pragma("unroll")                                                         \
    for (int j = 0; j < 2; j++) {                                             \
        int c = lc0 + j;                                                      \
        uint32_t d = dst0 + (((c) ^ (lrow & 7)) << 4);                        \
        cp_async16(d,         Ah + goffA + (kc) + c * 8);                     \
        cp_async16(d + 16384, Al + goffA + (kc) + c * 8);                     \
        cp_async16(d + 32768, Wh + goffW + (kc) + c * 8);                     \
        cp_async16(d + 49152, Wl + goffW + (kc) + c * 8);                     \
    }                                                                         \
} while (0)

    LOAD_CHUNK(0, 0);
    cp_commit();

    const int nk = E_DIM / 64;
    for (int kc = 0; kc < nk; kc++) {
        if (kc + 1 < nk) {
            LOAD_CHUNK((kc + 1) & 1, (kc + 1) * 64);
            cp_commit();
            cp_wait1();
        } else {
            cp_wait0();
        }
        __syncthreads();

        const uint32_t tb = sbase + (kc & 1) * 65536;
#pragma unroll
        for (int s = 0; s < 4; s++) {
            uint32_t a_h[2][4], a_l[2][4];
            const int ac = s * 2 + (lane >> 4);
#pragma unroll
            for (int mt = 0; mt < 2; mt++) {
                int r = wm + mt * 16 + (lane & 15);
                uint32_t ad = tb + r * 128 + ((ac ^ (r & 7)) << 4);
                ldsm4(ad, a_h[mt]);
                ldsm4(ad + 16384, a_l[mt]);
            }
            uint32_t b_h[4][2], b_l[4][2];
            const int grp = lane >> 3;
            const int bc = s * 2 + (grp & 1);
            const int br = wn + ((grp >> 1) << 3) + (lane & 7);
#pragma unroll
            for (int np = 0; np < 2; np++) {
                int r = br + np * 16;
                uint32_t bd = tb + 32768 + r * 128 + ((bc ^ (r & 7)) << 4);
                uint32_t q[4];
                ldsm4(bd, q);
                b_h[np * 2][0] = q[0]; b_h[np * 2][1] = q[1];
                b_h[np * 2 + 1][0] = q[2]; b_h[np * 2 + 1][1] = q[3];
                ldsm4(bd + 16384, q);
                b_l[np * 2][0] = q[0]; b_l[np * 2][1] = q[1];
                b_l[np * 2 + 1][0] = q[2]; b_l[np * 2 + 1][1] = q[3];
            }
#pragma unroll
            for (int mt = 0; mt < 2; mt++)
#pragma unroll
                for (int nt = 0; nt < 4; nt++) {
                    mma16816(acc[mt][nt], a_h[mt], b_h[nt]);
                    mma16816(acc[mt][nt], a_h[mt], b_l[nt]);
                    mma16816(acc[mt][nt], a_l[mt], b_h[nt]);
                }
        }
        __syncthreads();
    }
#undef LOAD_CHUNK

    // epilogue
#pragma unroll
    for (int mt = 0; mt < 2; mt++) {
        int r0 = bm + wm + mt * 16 + (lane >> 2);
#pragma unroll
        for (int nt = 0; nt < 4; nt++) {
            int cg = bn + wn + nt * 8 + ((lane & 3) << 1);
            float2 bb = *(const float2*)&bias[cg];
            float2 v0 = make_float2(acc[mt][nt][0] + bb.x, acc[mt][nt][1] + bb.y);
            float2 v1 = make_float2(acc[mt][nt][2] + bb.x, acc[mt][nt][3] + bb.y);
            *(float2*)&C[(size_t)r0 * E_DIM + cg] = v0;
            *(float2*)&C[(size_t)(r0 + 8) * E_DIM + cg] = v1;
        }
    }
}

// Fused 4-way projection: z=0:q z=1:k1 z=2:k2 z=3:v
extern "C" __global__ void __launch_bounds__(512)
proj_kernel(const float* __restrict__ bias) {
    const __nv_bfloat16 *Ah, *Al;
    float* C;
    int z = blockIdx.z;
    if (z == 0)      { Ah = in_q_h; Al = in_q_l; C = g_q;  }
    else if (z == 1) { Ah = in_k_h; Al = in_k_l; C = g_k1; }
    else if (z == 2) { Ah = in_k_h; Al = in_k_l; C = g_k2; }
    else             { Ah = in_v_h; Al = in_v_l; C = g_v;  }
    gemm_mma_body(Ah, Al, w_h + (size_t)z * WSZ, w_l + (size_t)z * WSZ,
                  bias + z * E_DIM, C);
}

extern "C" __global__ void __launch_bounds__(512)
out_kernel(const float* __restrict__ bias, float* __restrict__ C) {
    gemm_mma_body(ao_h, ao_l, w_h + (size_t)4 * WSZ, w_l + (size_t)4 * WSZ,
                  bias, C);
}

// ---------------------------------------------------------------------------
// Gaussian-kernel attention (unchanged). Block = (q-tile, head) x 256.
// ---------------------------------------------------------------------------
#define ATTN_SMEM ((5 * 64 * SPITCH + 3 * 64) * 4)

extern "C" __global__ void __launch_bounds__(256)
attn_kernel(const float* __restrict__ pi) {
    extern __shared__ float sm[];
    float* sq  = sm;
    float* sk1 = sq  + 64 * SPITCH;
    float* sk2 = sk1 + 64 * SPITCH;
    float* sv  = sk2 + 64 * SPITCH;
    float* sw  = sv  + 64 * SPITCH;
    float* q2s = sw  + 64 * SPITCH;
    float* k1n = q2s + 64;
    float* k2n = k1n + 64;

    const int tid = threadIdx.x;
    const int tx = tid & 15;
    const int ty = tid >> 4;
    const int qt = blockIdx.x;
    const int bh = blockIdx.y;
    const int b = bh >> 4;
    const int h = bh & 15;
    const int q0 = qt * 64;
    const size_t colbase = (size_t)h * HD;

    float p1 = fminf(fmaxf(fabsf(pi[h]), 1e-6f), 2.0f);
    float p2 = fminf(fmaxf(fabsf(pi[H_NUM + h]), 1e-6f), 2.0f);

#pragma unroll
    for (int i = 0; i < 4; i++) {
        int lin = i * 256 + tid;
        int r = lin >> 4;
        int c = (lin & 15) * 4;
        const float* src = g_q + ((size_t)(q0 + r) * B_SZ + b) * E_DIM + colbase + c;
        *(float4*)&sq[r * SPITCH + c] = *(const float4*)src;
    }
    __syncthreads();
    if (tid < 64) {
        float s = 0.0f;
#pragma unroll
        for (int d = 0; d < 64; d += 4) {
            float4 v4 = *(const float4*)&sq[tid * SPITCH + d];
            s += v4.x * v4.x + v4.y * v4.y + v4.z * v4.z + v4.w * v4.w;
        }
        q2s[tid] = s;
    }

    float accO[4][4] = {};
    float den[4] = {0.0f, 0.0f, 0.0f, 0.0f};

    for (int st = 0; st < 16; st++) {
        const int s0 = st * 64;
        __syncthreads();
#pragma unroll
        for (int i = 0; i < 4; i++) {
            int lin = i * 256 + tid;
            int r = lin >> 4;
            int c = (lin & 15) * 4;
            size_t goff = ((size_t)(s0 + r) * B_SZ + b) * E_DIM + colbase + c;
            *(float4*)&sk1[r * SPITCH + c] = *(const float4*)(g_k1 + goff);
            *(float4*)&sk2[r * SPITCH + c] = *(const float4*)(g_k2 + goff);
            *(float4*)&sv [r * SPITCH + c] = *(const float4*)(g_v  + goff);
        }
        __syncthreads();
        if (tid < 128) {
            const float* krow = ((tid < 64) ? sk1 : sk2) + (tid & 63) * SPITCH;
            float s = 0.0f;
#pragma unroll
            for (int d = 0; d < 64; d += 4) {
                float4 v4 = *(const float4*)&krow[d];
                s += v4.x * v4.x + v4.y * v4.y + v4.z * v4.z + v4.w * v4.w;
            }
            ((tid < 64) ? k1n : k2n)[tid & 63] = s;
        }
        __syncthreads();

        float a1[4][4] = {}, a2[4][4] = {};
#pragma unroll
        for (int d = 0; d < 64; d += 4) {
            float4 qa[4];
#pragma unroll
            for (int i = 0; i < 4; i++)
                qa[i] = *(const float4*)&sq[(ty * 4 + i) * SPITCH + d];
#pragma unroll
            for (int j = 0; j < 4; j++) {
                float4 ka = *(const float4*)&sk1[(tx * 4 + j) * SPITCH + d];
                float4 kb = *(const float4*)&sk2[(tx * 4 + j) * SPITCH + d];
#pragma unroll
                for (int i = 0; i < 4; i++) {
                    a1[i][j] += qa[i].x * ka.x + qa[i].y * ka.y
                              + qa[i].z * ka.z + qa[i].w * ka.w;
                    a2[i][j] += qa[i].x * kb.x + qa[i].y * kb.y
                              + qa[i].z * kb.z + qa[i].w * kb.w;
                }
            }
        }

#pragma unroll
        for (int i = 0; i < 4; i++) {
            float q2v = q2s[ty * 4 + i];
            float wv_[4];
#pragma unroll
            for (int j = 0; j < 4; j++) {
                int s_ = tx * 4 + j;
                float d1 = q2v + k1n[s_] - 2.0f * a1[i][j];
                float d2 = q2v + k2n[s_] - 2.0f * a2[i][j];
                float w = p1 * __expf(-0.0625f * d1) + p2 * __expf(-0.1875f * d2);
                den[i] += w;
                wv_[j] = w;
            }
            *(float4*)&sw[(ty * 4 + i) * SPITCH + tx * 4] =
                make_float4(wv_[0], wv_[1], wv_[2], wv_[3]);
        }
        __syncthreads();

#pragma unroll 4
        for (int s_ = 0; s_ < 64; s_++) {
            float4 v4 = *(const float4*)&sv[s_ * SPITCH + tx * 4];
#pragma unroll
            for (int i = 0; i < 4; i++) {
                float w = sw[(ty * 4 + i) * SPITCH + s_];
                accO[i][0] += w * v4.x;
                accO[i][1] += w * v4.y;
                accO[i][2] += w * v4.z;
                accO[i][3] += w * v4.w;
            }
        }
    }

#pragma unroll
    for (int i = 0; i < 4; i++) {
#pragma unroll
        for (int m = 1; m < 16; m <<= 1)
            den[i] += __shfl_xor_sync(0xffffffffu, den[i], m);
    }

#pragma unroll
    for (int i = 0; i < 4; i++) {
        float inv = 1.0f / (den[i] + 1e-6f);
        int t = q0 + ty * 4 + i;
        float4 o = make_float4(accO[i][0] * inv, accO[i][1] * inv,
                               accO[i][2] * inv, accO[i][3] * inv);
        *(float4*)&g_ao[((size_t)t * B_SZ + b) * E_DIM + colbase + tx * 4] = o;
    }
}

// ---------------------------------------------------------------------------
extern "C" void kernel_launch(void* const* d_in, const int* in_sizes, int n_in,
                              void* d_out, int out_size) {
    const float* query = (const float*)d_in[0];
    const float* key   = (const float*)d_in[1];
    const float* value = (const float*)d_in[2];
    const float* wq    = (const float*)d_in[3];
    const float* wk1   = (const float*)d_in[4];
    const float* wk2   = (const float*)d_in[5];
    const float* wv    = (const float*)d_in[6];
    const float* bias  = (const float*)d_in[7];
    const float* wo    = (const float*)d_in[8];
    const float* bo    = (const float*)d_in[9];
    const float* pi    = (const float*)d_in[10];
    float* out = (float*)d_out;

    cudaFuncSetAttribute(proj_kernel,
                         cudaFuncAttributeMaxDynamicSharedMemorySize, GEMM_SMEM);
    cudaFuncSetAttribute(out_kernel,
                         cudaFuncAttributeMaxDynamicSharedMemorySize, GEMM_SMEM);
    cudaFuncSetAttribute(attn_kernel,
                         cudaFuncAttributeMaxDynamicSharedMemorySize, ATTN_SMEM);

    // resolve device-global bf16 buffers
    __nv_bfloat16 *p_qh, *p_ql, *p_kh, *p_kl, *p_vh, *p_vl, *p_wh, *p_wl,
                  *p_aoh, *p_aol;
    cudaGetSymbolAddress((void**)&p_qh, in_q_h);
    cudaGetSymbolAddress((void**)&p_ql, in_q_l);
    cudaGetSymbolAddress((void**)&p_kh, in_k_h);
    cudaGetSymbolAddress((void**)&p_kl, in_k_l);
    cudaGetSymbolAddress((void**)&p_vh, in_v_h);
    cudaGetSymbolAddress((void**)&p_vl, in_v_l);
    cudaGetSymbolAddress((void**)&p_wh, w_h);
    cudaGetSymbolAddress((void**)&p_wl, w_l);
    cudaGetSymbolAddress((void**)&p_aoh, ao_h);
    cudaGetSymbolAddress((void**)&p_aol, ao_l);
    float* p_gao;
    cudaGetSymbolAddress((void**)&p_gao, g_ao);

    const int n4a = NELEM / 4;          // activations: 1048576 float4
    const int n4w = WSZ / 4;            // weights: 262144 float4
    split_kernel<<<n4a / 256, 256>>>(query, p_qh, p_ql, n4a);
    split_kernel<<<n4a / 256, 256>>>(key,   p_kh, p_kl, n4a);
    split_kernel<<<n4a / 256, 256>>>(value, p_vh, p_vl, n4a);
    split_kernel<<<n4w / 256, 256>>>(wq,  p_wh + 0 * (size_t)WSZ, p_wl + 0 * (size_t)WSZ, n4w);
    split_kernel<<<n4w / 256, 256>>>(wk1, p_wh + 1 * (size_t)WSZ, p_wl + 1 * (size_t)WSZ, n4w);
    split_kernel<<<n4w / 256, 256>>>(wk2, p_wh + 2 * (size_t)WSZ, p_wl + 2 * (size_t)WSZ, n4w);
    split_kernel<<<n4w / 256, 256>>>(wv,  p_wh + 3 * (size_t)WSZ, p_wl + 3 * (size_t)WSZ, n4w);
    split_kernel<<<n4w / 256, 256>>>(wo,  p_wh + 4 * (size_t)WSZ, p_wl + 4 * (size_t)WSZ, n4w);

    dim3 gproj(8, 32, 4);
    proj_kernel<<<gproj, 512, GEMM_SMEM>>>(bias);

    dim3 gattn(16, 64);
    attn_kernel<<<gattn, 256, ATTN_SMEM>>>(pi);

    split_kernel<<<n4a / 256, 256>>>(p_gao, p_aoh, p_aol, n4a);

    dim3 gout(8, 32);
    out_kernel<<<gout, 512, GEMM_SMEM>>>(bo, out);
}

// round 7
// speedup vs baseline: 3.2121x; 2.4011x over previous
#include <cuda_runtime.h>
#include <cuda_bf16.h>
#include <math.h>
#include <cstdint>

#define E_DIM 1024
#define M_DIM 4096
#define H_NUM 16
#define HD 64
#define B_SZ 4
#define NELEM (M_DIM * E_DIM)
#define WSZ (E_DIM * E_DIM)

// bf16 hi/lo split buffers (inputs to GEMMs)
__device__ __nv_bfloat16 in_q_h[NELEM], in_q_l[NELEM];
__device__ __nv_bfloat16 in_k_h[NELEM], in_k_l[NELEM];
__device__ __nv_bfloat16 in_v_h[NELEM], in_v_l[NELEM];
__device__ __nv_bfloat16 w_h[5 * WSZ],  w_l[5 * WSZ];

// proj outputs (bf16 hi/lo), attention output (bf16 hi/lo)
__device__ __nv_bfloat16 o_q_h[NELEM],  o_q_l[NELEM];
__device__ __nv_bfloat16 o_k1_h[NELEM], o_k1_l[NELEM];
__device__ __nv_bfloat16 o_k2_h[NELEM], o_k2_l[NELEM];
__device__ __nv_bfloat16 o_v_h[NELEM],  o_v_l[NELEM];
__device__ __nv_bfloat16 ao_h[NELEM],   ao_l[NELEM];

// norms: [bh*1024 + t]
__device__ float n_q2[64 * 1024];
__device__ float n_k1[64 * 1024];
__device__ float n_k2[64 * 1024];

// ===========================================================================
// helpers
// ===========================================================================
__device__ __forceinline__ uint32_t smem_u32(const void* p) {
    uint32_t a;
    asm("{ .reg .u64 t; cvta.to.shared.u64 t, %1; cvt.u32.u64 %0, t; }"
        : "=r"(a) : "l"(p));
    return a;
}
__device__ __forceinline__ void cp_async16(uint32_t dst, const void* src) {
    asm volatile("cp.async.cg.shared.global [%0], [%1], 16;"
                 :: "r"(dst), "l"(src));
}
__device__ __forceinline__ void cp_commit() {
    asm volatile("cp.async.commit_group;" ::: "memory");
}
__device__ __forceinline__ void cp_wait1() {
    asm volatile("cp.async.wait_group 1;" ::: "memory");
}
__device__ __forceinline__ void cp_wait0() {
    asm volatile("cp.async.wait_group 0;" ::: "memory");
}
__device__ __forceinline__ void ldsm4(uint32_t addr, uint32_t* r) {
    asm volatile("ldmatrix.sync.aligned.m8n8.x4.shared.b16 {%0,%1,%2,%3}, [%4];"
                 : "=r"(r[0]), "=r"(r[1]), "=r"(r[2]), "=r"(r[3]) : "r"(addr));
}
__device__ __forceinline__ void ldsm4t(uint32_t addr, uint32_t* r) {
    asm volatile("ldmatrix.sync.aligned.m8n8.x4.trans.shared.b16 {%0,%1,%2,%3}, [%4];"
                 : "=r"(r[0]), "=r"(r[1]), "=r"(r[2]), "=r"(r[3]) : "r"(addr));
}
__device__ __forceinline__ void mma16816(float* d, const uint32_t* a,
                                         const uint32_t* b) {
    asm volatile(
        "mma.sync.aligned.m16n8k16.row.col.f32.bf16.bf16.f32 "
        "{%0,%1,%2,%3}, {%4,%5,%6,%7}, {%8,%9}, {%0,%1,%2,%3};"
        : "+f"(d[0]), "+f"(d[1]), "+f"(d[2]), "+f"(d[3])
        : "r"(a[0]), "r"(a[1]), "r"(a[2]), "r"(a[3]), "r"(b[0]), "r"(b[1]));
}
__device__ __forceinline__ void split2(float x, float y, uint32_t& hi, uint32_t& lo) {
    __nv_bfloat162 h = __float22bfloat162_rn(make_float2(x, y));
    float2 f = __bfloat1622float2(h);
    __nv_bfloat162 l = __float22bfloat162_rn(make_float2(x - f.x, y - f.y));
    hi = *reinterpret_cast<uint32_t*>(&h);
    lo = *reinterpret_cast<uint32_t*>(&l);
}

// ===========================================================================
// fp32 -> bf16 hi/lo split (for harness inputs / weights)
// ===========================================================================
extern "C" __global__ void __launch_bounds__(256)
split_kernel(const float* __restrict__ src, __nv_bfloat16* __restrict__ hi,
             __nv_bfloat16* __restrict__ lo, int n4) {
    int i = blockIdx.x * blockDim.x + threadIdx.x;
    if (i >= n4) return;
    float4 v = ((const float4*)src)[i];
    uint32_t h0, l0, h1, l1;
    split2(v.x, v.y, h0, l0);
    split2(v.z, v.w, h1, l1);
    ((uint32_t*)hi)[i * 2]     = h0;
    ((uint32_t*)hi)[i * 2 + 1] = h1;
    ((uint32_t*)lo)[i * 2]     = l0;
    ((uint32_t*)lo)[i * 2 + 1] = l1;
}

// ===========================================================================
// mma.sync GEMM: C[M,N] = A[M,K] @ W[N,K]^T + bias  (bf16 hi/lo, fp32 acc)
// CTA 128x128, K chunk 64, 512 threads. Epilogue: fp32 OR bf16 hi/lo.
// ===========================================================================
#define GEMM_SMEM 131072

__device__ __forceinline__ void gemm_mma_body(
    const __nv_bfloat16* __restrict__ Ah, const __nv_bfloat16* __restrict__ Al,
    const __nv_bfloat16* __restrict__ Wh, const __nv_bfloat16* __restrict__ Wl,
    const float* __restrict__ bias, float* __restrict__ Cf,
    __nv_bfloat16* __restrict__ Ch, __nv_bfloat16* __restrict__ Cl) {
    extern __shared__ char smem[];
    const uint32_t sbase = smem_u32(smem);
    const int tid = threadIdx.x;
    const int lane = tid & 31;
    const int wid = tid >> 5;
    const int bm = blockIdx.y * 128;
    const int bn = blockIdx.x * 128;
    const int wm = (wid & 3) * 32;
    const int wn = (wid >> 2) * 32;

    const int lrow = tid >> 2;
    const int lc0 = (tid & 3) * 2;
    const size_t goffA = (size_t)(bm + lrow) * E_DIM;
    const size_t goffW = (size_t)(bn + lrow) * E_DIM;

    float acc[2][4][4];
#pragma unroll
    for (int mt = 0; mt < 2; mt++)
#pragma unroll
        for (int nt = 0; nt < 4; nt++)
#pragma unroll
            for (int e = 0; e < 4; e++) acc[mt][nt][e] = 0.0f;

#define LOAD_CHUNK(buf, kc) do {                                              \
    uint32_t dst0 = sbase + (buf) * 65536 + lrow * 128;                       \
    _Pragma("unroll")                                                         \
    for (int j = 0; j < 2; j++) {                                             \
        int c = lc0 + j;                                                      \
        uint32_t d = dst0 + (((c) ^ (lrow & 7)) << 4);                        \
        cp_async16(d,         Ah + goffA + (kc) + c * 8);                     \
        cp_async16(d + 16384, Al + goffA + (kc) + c * 8);                     \
        cp_async16(d + 32768, Wh + goffW + (kc) + c * 8);                     \
        cp_async16(d + 49152, Wl + goffW + (kc) + c * 8);                     \
    }                                                                         \
} while (0)

    LOAD_CHUNK(0, 0);
    cp_commit();

    const int nk = E_DIM / 64;
    for (int kc = 0; kc < nk; kc++) {
        if (kc + 1 < nk) {
            LOAD_CHUNK((kc + 1) & 1, (kc + 1) * 64);
            cp_commit();
            cp_wait1();
        } else {
            cp_wait0();
        }
        __syncthreads();

        const uint32_t tb = sbase + (kc & 1) * 65536;
#pragma unroll
        for (int s = 0; s < 4; s++) {
            uint32_t a_h[2][4], a_l[2][4];
            const int ac = s * 2 + (lane >> 4);
#pragma unroll
            for (int mt = 0; mt < 2; mt++) {
                int r = wm + mt * 16 + (lane & 15);
                uint32_t ad = tb + r * 128 + ((ac ^ (r & 7)) << 4);
                ldsm4(ad, a_h[mt]);
                ldsm4(ad + 16384, a_l[mt]);
            }
            uint32_t b_h[4][2], b_l[4][2];
            const int grp = lane >> 3;
            const int bc = s * 2 + (grp & 1);
            const int br = wn + ((grp >> 1) << 3) + (lane & 7);
#pragma unroll
            for (int np = 0; np < 2; np++) {
                int r = br + np * 16;
                uint32_t bd = tb + 32768 + r * 128 + ((bc ^ (r & 7)) << 4);
                uint32_t q[4];
                ldsm4(bd, q);
                b_h[np * 2][0] = q[0]; b_h[np * 2][1] = q[1];
                b_h[np * 2 + 1][0] = q[2]; b_h[np * 2 + 1][1] = q[3];
                ldsm4(bd + 16384, q);
                b_l[np * 2][0] = q[0]; b_l[np * 2][1] = q[1];
                b_l[np * 2 + 1][0] = q[2]; b_l[np * 2 + 1][1] = q[3];
            }
#pragma unroll
            for (int mt = 0; mt < 2; mt++)
#pragma unroll
                for (int nt = 0; nt < 4; nt++) {
                    mma16816(acc[mt][nt], a_h[mt], b_h[nt]);
                    mma16816(acc[mt][nt], a_h[mt], b_l[nt]);
                    mma16816(acc[mt][nt], a_l[mt], b_h[nt]);
                }
        }
        __syncthreads();
    }
#undef LOAD_CHUNK

    // epilogue
#pragma unroll
    for (int mt = 0; mt < 2; mt++) {
        int r0 = bm + wm + mt * 16 + (lane >> 2);
#pragma unroll
        for (int nt = 0; nt < 4; nt++) {
            int cg = bn + wn + nt * 8 + ((lane & 3) << 1);
            float2 bb = *(const float2*)&bias[cg];
            float v00 = acc[mt][nt][0] + bb.x, v01 = acc[mt][nt][1] + bb.y;
            float v10 = acc[mt][nt][2] + bb.x, v11 = acc[mt][nt][3] + bb.y;
            if (Cf) {
                *(float2*)&Cf[(size_t)r0 * E_DIM + cg] = make_float2(v00, v01);
                *(float2*)&Cf[(size_t)(r0 + 8) * E_DIM + cg] = make_float2(v10, v11);
            } else {
                uint32_t h0, l0, h1, l1;
                split2(v00, v01, h0, l0);
                split2(v10, v11, h1, l1);
                *(uint32_t*)&Ch[(size_t)r0 * E_DIM + cg] = h0;
                *(uint32_t*)&Cl[(size_t)r0 * E_DIM + cg] = l0;
                *(uint32_t*)&Ch[(size_t)(r0 + 8) * E_DIM + cg] = h1;
                *(uint32_t*)&Cl[(size_t)(r0 + 8) * E_DIM + cg] = l1;
            }
        }
    }
}

// Fused 4-way projection: z=0:q z=1:k1 z=2:k2 z=3:v  -> bf16 hi/lo outputs
extern "C" __global__ void __launch_bounds__(512)
proj_kernel(const float* __restrict__ bias) {
    const __nv_bfloat16 *Ah, *Al;
    __nv_bfloat16 *Ch, *Cl;
    int z = blockIdx.z;
    if (z == 0)      { Ah = in_q_h; Al = in_q_l; Ch = o_q_h;  Cl = o_q_l;  }
    else if (z == 1) { Ah = in_k_h; Al = in_k_l; Ch = o_k1_h; Cl = o_k1_l; }
    else if (z == 2) { Ah = in_k_h; Al = in_k_l; Ch = o_k2_h; Cl = o_k2_l; }
    else             { Ah = in_v_h; Al = in_v_l; Ch = o_v_h;  Cl = o_v_l;  }
    gemm_mma_body(Ah, Al, w_h + (size_t)z * WSZ, w_l + (size_t)z * WSZ,
                  bias + z * E_DIM, nullptr, Ch, Cl);
}

extern "C" __global__ void __launch_bounds__(512)
out_kernel(const float* __restrict__ bias, float* __restrict__ C) {
    gemm_mma_body(ao_h, ao_l, w_h + (size_t)4 * WSZ, w_l + (size_t)4 * WSZ,
                  bias, C, nullptr, nullptr);
}

// ===========================================================================
// norm kernel: per-head squared norms of q, k1, k2 (from hi+lo)
// ===========================================================================
extern "C" __global__ void __launch_bounds__(256)
norm_kernel() {
    const int z = blockIdx.y;
    const __nv_bfloat16 *H, *L;
    float* N;
    if (z == 0)      { H = o_q_h;  L = o_q_l;  N = n_q2; }
    else if (z == 1) { H = o_k1_h; L = o_k1_l; N = n_k1; }
    else             { H = o_k2_h; L = o_k2_l; N = n_k2; }
    const int idx = blockIdx.x * 256 + threadIdx.x;      // 0..65535
    const int h = idx & 15, tb = idx >> 4;
    const size_t base = (size_t)tb * E_DIM + h * HD;
    float s = 0.0f;
#pragma unroll
    for (int g = 0; g < 8; g++) {
        uint4 uh = *(const uint4*)(H + base + g * 8);
        uint4 ul = *(const uint4*)(L + base + g * 8);
#define ACC2(uw, lw) { \
        float2 fa = __bfloat1622float2(*(__nv_bfloat162*)&(uw)); \
        float2 fc = __bfloat1622float2(*(__nv_bfloat162*)&(lw)); \
        float v0 = fa.x + fc.x, v1 = fa.y + fc.y; \
        s = fmaf(v0, v0, s); s = fmaf(v1, v1, s); }
        ACC2(uh.x, ul.x) ACC2(uh.y, ul.y) ACC2(uh.z, ul.z) ACC2(uh.w, ul.w)
#undef ACC2
    }
    N[(size_t)((tb & 3) * 16 + h) * 1024 + (tb >> 2)] = s;
}

// ===========================================================================
// Tensorized Gaussian-kernel attention.
// Block = (64 q rows, bh), 256 threads = 8 warps (4 m-strips x 2 n-strips).
// ===========================================================================
#define AT_SQH 0
#define AT_SQL 8192
#define AT_Q2  16384
#define AT_BUF0 16640
#define AT_BUFSZ 49664
#define AT_K1H 0
#define AT_K1L 8192
#define AT_K2H 16384
#define AT_K2L 24576
#define AT_VH  32768
#define AT_VL  40960
#define AT_N1  49152
#define AT_N2  49408
#define ATTN_SMEM (AT_BUF0 + 2 * AT_BUFSZ)

extern "C" __global__ void __launch_bounds__(256)
attn_kernel(const float* __restrict__ pi) {
    extern __shared__ char smem[];
    const uint32_t sb = smem_u32(smem);
    const int tid = threadIdx.x;
    const int lane = tid & 31;
    const int wid = tid >> 5;
    const int wm = (wid & 3) * 16;
    const int wn = wid >> 2;
    const int qt = blockIdx.x;
    const int bh = blockIdx.y;
    const int b = bh >> 4;
    const int h = bh & 15;
    const int q0 = qt * 64;

    const float p1 = fminf(fmaxf(fabsf(pi[h]), 1e-6f), 2.0f);
    const float p2 = fminf(fmaxf(fabsf(pi[H_NUM + h]), 1e-6f), 2.0f);

    const int lr = tid >> 2;
    const int lc = (tid & 3) * 2;
    const size_t grow = (size_t)h * HD;

#define LOADKV(buf, s0) do {                                                      \
    uint32_t bdst = sb + AT_BUF0 + (buf) * AT_BUFSZ;                              \
    size_t gsrc = ((size_t)((s0) + lr) * B_SZ + b) * E_DIM + grow;                \
    _Pragma("unroll")                                                             \
    for (int j = 0; j < 2; j++) {                                                 \
        int c = lc + j;                                                           \
        uint32_t d = bdst + lr * 128 + ((c ^ (lr & 7)) << 4);                     \
        cp_async16(d + AT_K1H, o_k1_h + gsrc + c * 8);                            \
        cp_async16(d + AT_K1L, o_k1_l + gsrc + c * 8);                            \
        cp_async16(d + AT_K2H, o_k2_h + gsrc + c * 8);                            \
        cp_async16(d + AT_K2L, o_k2_l + gsrc + c * 8);                            \
        cp_async16(d + AT_VH,  o_v_h  + gsrc + c * 8);                            \
        cp_async16(d + AT_VL,  o_v_l  + gsrc + c * 8);                            \
    }                                                                             \
    if (tid < 16)                                                                 \
        cp_async16(bdst + AT_N1 + tid * 16, n_k1 + (size_t)bh * 1024 + (s0) + tid * 4); \
    else if (tid < 32)                                                            \
        cp_async16(bdst + AT_N2 + (tid - 16) * 16, n_k2 + (size_t)bh * 1024 + (s0) + (tid - 16) * 4); \
} while (0)

    // Q tiles + q2 + first KV buffer in one group
    {
        size_t g = ((size_t)(q0 + lr) * B_SZ + b) * E_DIM + grow;
#pragma unroll
        for (int j = 0; j < 2; j++) {
            int c = lc + j;
            uint32_t sw = (uint32_t)((c ^ (lr & 7)) << 4);
            cp_async16(sb + AT_SQH + lr * 128 + sw, o_q_h + g + c * 8);
            cp_async16(sb + AT_SQL + lr * 128 + sw, o_q_l + g + c * 8);
        }
        if (tid < 16)
            cp_async16(sb + AT_Q2 + tid * 16, n_q2 + (size_t)bh * 1024 + q0 + tid * 4);
    }
    LOADKV(0, 0);
    cp_commit();

    float O[4][4];
#pragma unroll
    for (int nt = 0; nt < 4; nt++)
#pragma unroll
        for (int e = 0; e < 4; e++) O[nt][e] = 0.0f;
    float den0 = 0.0f, den1 = 0.0f;

    for (int st = 0; st < 16; st++) {
        cp_wait0();
        __syncthreads();
        if (st < 15) { LOADKV((st + 1) & 1, (st + 1) * 64); cp_commit(); }

        const uint32_t bb = sb + AT_BUF0 + (st & 1) * AT_BUFSZ;
        char* bbp = smem + AT_BUF0 + (st & 1) * AT_BUFSZ;

        float S1[4][4], S2[4][4];
#pragma unroll
        for (int nt = 0; nt < 4; nt++)
#pragma unroll
            for (int e = 0; e < 4; e++) { S1[nt][e] = 0.0f; S2[nt][e] = 0.0f; }

        // ---- QK ----
#pragma unroll
        for (int kk = 0; kk < 4; kk++) {
            uint32_t ah[4], al[4];
            {
                int r = wm + (lane & 15);
                int c = kk * 2 + (lane >> 4);
                uint32_t ad = sb + AT_SQH + r * 128 + ((c ^ (r & 7)) << 4);
                ldsm4(ad, ah);
                ldsm4(ad + 8192, al);
            }
            uint32_t b1h[4][2], b1l[4][2], b2h[4][2], b2l[4][2];
            {
                const int grp = lane >> 3;
                const int c = kk * 2 + (grp & 1);
                const int rb = wn * 32 + ((grp >> 1) << 3) + (lane & 7);
#pragma unroll
                for (int np = 0; np < 2; np++) {
                    int r = rb + np * 16;
                    uint32_t ra = bb + r * 128 + ((c ^ (r & 7)) << 4);
                    uint32_t q[4];
                    ldsm4(ra + AT_K1H, q);
                    b1h[np*2][0]=q[0]; b1h[np*2][1]=q[1]; b1h[np*2+1][0]=q[2]; b1h[np*2+1][1]=q[3];
                    ldsm4(ra + AT_K1L, q);
                    b1l[np*2][0]=q[0]; b1l[np*2][1]=q[1]; b1l[np*2+1][0]=q[2]; b1l[np*2+1][1]=q[3];
                    ldsm4(ra + AT_K2H, q);
                    b2h[np*2][0]=q[0]; b2h[np*2][1]=q[1]; b2h[np*2+1][0]=q[2]; b2h[np*2+1][1]=q[3];
                    ldsm4(ra + AT_K2L, q);
                    b2l[np*2][0]=q[0]; b2l[np*2][1]=q[1]; b2l[np*2+1][0]=q[2]; b2l[np*2+1][1]=q[3];
                }
            }
#pragma unroll
            for (int nt = 0; nt < 4; nt++) {
                mma16816(S1[nt], ah, b1h[nt]);
                mma16816(S1[nt], ah, b1l[nt]);
                mma16816(S1[nt], al, b1h[nt]);
                mma16816(S2[nt], ah, b2h[nt]);
                mma16816(S2[nt], ah, b2l[nt]);
                mma16816(S2[nt], al, b2h[nt]);
            }
        }
        __syncthreads();   // all K1 reads done before w overwrites that region

        // ---- weights: w = p1 e1 + p2 e2, split to bf16 hi/lo into K1 region ----
        {
            const int r0 = wm + (lane >> 2);
            const float q2a = *(const float*)(smem + AT_Q2 + r0 * 4);
            const float q2b = *(const float*)(smem + AT_Q2 + (r0 + 8) * 4);
            const float* k1p = (const float*)(bbp + AT_N1);
            const float* k2p = (const float*)(bbp + AT_N2);
#pragma unroll
            for (int nt = 0; nt < 4; nt++) {
                const int cp0 = wn * 32 + nt * 8 + 2 * (lane & 3);
                const float k1a = k1p[cp0], k1b = k1p[cp0 + 1];
                const float k2a = k2p[cp0], k2b = k2p[cp0 + 1];
                float w00 = p1 * __expf(-0.0625f * (q2a + k1a - 2.0f * S1[nt][0]))
                          + p2 * __expf(-0.1875f * (q2a + k2a - 2.0f * S2[nt][0]));
                float w01 = p1 * __expf(-0.0625f * (q2a + k1b - 2.0f * S1[nt][1]))
                          + p2 * __expf(-0.1875f * (q2a + k2b - 2.0f * S2[nt][1]));
                float w10 = p1 * __expf(-0.0625f * (q2b + k1a - 2.0f * S1[nt][2]))
                          + p2 * __expf(-0.1875f * (q2b + k2a - 2.0f * S2[nt][2]));
                float w11 = p1 * __expf(-0.0625f * (q2b + k1b - 2.0f * S1[nt][3]))
                          + p2 * __expf(-0.1875f * (q2b + k2b - 2.0f * S2[nt][3]));
                den0 += w00 + w01;
                den1 += w10 + w11;
                uint32_t h0, l0, h1, l1;
                split2(w00, w01, h0, l0);
                split2(w10, w11, h1, l1);
                const int g = wn * 4 + nt;
                const uint32_t wo0 = r0 * 128 + ((g ^ (r0 & 7)) << 4) + (lane & 3) * 4;
                *(uint32_t*)(bbp + AT_K1H + wo0) = h0;
                *(uint32_t*)(bbp + AT_K1L + wo0) = l0;
                *(uint32_t*)(bbp + AT_K1H + wo0 + 1024) = h1;
                *(uint32_t*)(bbp + AT_K1L + wo0 + 1024) = l1;
            }
        }
        __syncthreads();

        // ---- AV: O += w @ V (V via ldmatrix.trans) ----
#pragma unroll
        for (int kk = 0; kk < 4; kk++) {
            uint32_t ah[4], al[4];
            {
                int r = wm + (lane & 15);
                int c = kk * 2 + (lane >> 4);
                uint32_t ad = bb + AT_K1H + r * 128 + ((c ^ (r & 7)) << 4);
                ldsm4(ad, ah);
                ldsm4(ad + 8192, al);
            }
            uint32_t bvh[4][2], bvl[4][2];
            {
                int r = kk * 16 + (lane & 15);
                int g0 = wn * 4 + (lane >> 4);
                uint32_t rowa = bb + AT_VH + r * 128;
                uint32_t q[4];
                ldsm4t(rowa + ((g0 ^ (r & 7)) << 4), q);
                bvh[0][0]=q[0]; bvh[0][1]=q[1]; bvh[1][0]=q[2]; bvh[1][1]=q[3];
                ldsm4t(rowa + (((g0 + 2) ^ (r & 7)) << 4), q);
                bvh[2][0]=q[0]; bvh[2][1]=q[1]; bvh[3][0]=q[2]; bvh[3][1]=q[3];
                rowa += 8192;
                ldsm4t(rowa + ((g0 ^ (r & 7)) << 4), q);
                bvl[0][0]=q[0]; bvl[0][1]=q[1]; bvl[1][0]=q[2]; bvl[1][1]=q[3];
                ldsm4t(rowa + (((g0 + 2) ^ (r & 7)) << 4), q);
                bvl[2][0]=q[0]; bvl[2][1]=q[1]; bvl[3][0]=q[2]; bvl[3][1]=q[3];
            }
#pragma unroll
            for (int nt = 0; nt < 4; nt++) {
                mma16816(O[nt], ah, bvh[nt]);
                mma16816(O[nt], ah, bvl[nt]);
                mma16816(O[nt], al, bvh[nt]);
            }
        }
    }
#undef LOADKV

    // ---- denominator reduce + normalized output (bf16 hi/lo) ----
    den0 += __shfl_xor_sync(0xffffffffu, den0, 1);
    den0 += __shfl_xor_sync(0xffffffffu, den0, 2);
    den1 += __shfl_xor_sync(0xffffffffu, den1, 1);
    den1 += __shfl_xor_sync(0xffffffffu, den1, 2);
    float* dens = (float*)(smem + AT_SQH);
    const int r0 = wm + (lane >> 2);
    __syncthreads();
    if ((lane & 3) == 0) {
        dens[r0 * 2 + wn] = den0;
        dens[(r0 + 8) * 2 + wn] = den1;
    }
    __syncthreads();
    const float ia = 1.0f / (dens[r0 * 2] + dens[r0 * 2 + 1] + 1e-6f);
    const float ib = 1.0f / (dens[(r0 + 8) * 2] + dens[(r0 + 8) * 2 + 1] + 1e-6f);
#pragma unroll
    for (int nt = 0; nt < 4; nt++) {
        const int cp0 = wn * 32 + nt * 8 + 2 * (lane & 3);
        size_t i0 = ((size_t)(q0 + r0) * B_SZ + b) * E_DIM + grow + cp0;
        size_t i1 = i0 + (size_t)8 * B_SZ * E_DIM;
        uint32_t h0, l0, h1, l1;
        split2(O[nt][0] * ia, O[nt][1] * ia, h0, l0);
        split2(O[nt][2] * ib, O[nt][3] * ib, h1, l1);
        *(uint32_t*)&ao_h[i0] = h0; *(uint32_t*)&ao_l[i0] = l0;
        *(uint32_t*)&ao_h[i1] = h1; *(uint32_t*)&ao_l[i1] = l1;
    }
}

// ---------------------------------------------------------------------------
extern "C" void kernel_launch(void* const* d_in, const int* in_sizes, int n_in,
                              void* d_out, int out_size) {
    const float* query = (const float*)d_in[0];
    const float* key   = (const float*)d_in[1];
    const float* value = (const float*)d_in[2];
    const float* wq    = (const float*)d_in[3];
    const float* wk1   = (const float*)d_in[4];
    const float* wk2   = (const float*)d_in[5];
    const float* wv    = (const float*)d_in[6];
    const float* bias  = (const float*)d_in[7];
    const float* wo    = (const float*)d_in[8];
    const float* bo    = (const float*)d_in[9];
    const float* pi    = (const float*)d_in[10];
    float* out = (float*)d_out;

    cudaFuncSetAttribute(proj_kernel,
                         cudaFuncAttributeMaxDynamicSharedMemorySize, GEMM_SMEM);
    cudaFuncSetAttribute(out_kernel,
                         cudaFuncAttributeMaxDynamicSharedMemorySize, GEMM_SMEM);
    cudaFuncSetAttribute(attn_kernel,
                         cudaFuncAttributeMaxDynamicSharedMemorySize, ATTN_SMEM);

    __nv_bfloat16 *p_qh, *p_ql, *p_kh, *p_kl, *p_vh, *p_vl, *p_wh, *p_wl;
    cudaGetSymbolAddress((void**)&p_qh, in_q_h);
    cudaGetSymbolAddress((void**)&p_ql, in_q_l);
    cudaGetSymbolAddress((void**)&p_kh, in_k_h);
    cudaGetSymbolAddress((void**)&p_kl, in_k_l);
    cudaGetSymbolAddress((void**)&p_vh, in_v_h);
    cudaGetSymbolAddress((void**)&p_vl, in_v_l);
    cudaGetSymbolAddress((void**)&p_wh, w_h);
    cudaGetSymbolAddress((void**)&p_wl, w_l);

    const int n4a = NELEM / 4;
    const int n4w = WSZ / 4;
    split_kernel<<<n4a / 256, 256>>>(query, p_qh, p_ql, n4a);
    split_kernel<<<n4a / 256, 256>>>(key,   p_kh, p_kl, n4a);
    split_kernel<<<n4a / 256, 256>>>(value, p_vh, p_vl, n4a);
    split_kernel<<<n4w / 256, 256>>>(wq,  p_wh + 0 * (size_t)WSZ, p_wl + 0 * (size_t)WSZ, n4w);
    split_kernel<<<n4w / 256, 256>>>(wk1, p_wh + 1 * (size_t)WSZ, p_wl + 1 * (size_t)WSZ, n4w);
    split_kernel<<<n4w / 256, 256>>>(wk2, p_wh + 2 * (size_t)WSZ, p_wl + 2 * (size_t)WSZ, n4w);
    split_kernel<<<n4w / 256, 256>>>(wv,  p_wh + 3 * (size_t)WSZ, p_wl + 3 * (size_t)WSZ, n4w);
    split_kernel<<<n4w / 256, 256>>>(wo,  p_wh + 4 * (size_t)WSZ, p_wl + 4 * (size_t)WSZ, n4w);

    dim3 gproj(8, 32, 4);
    proj_kernel<<<gproj, 512, GEMM_SMEM>>>(bias);

    dim3 gnorm(256, 3);
    norm_kernel<<<gnorm, 256>>>();

    dim3 gattn(16, 64);
    attn_kernel<<<gattn, 256, ATTN_SMEM>>>(pi);

    dim3 gout(8, 32);
    out_kernel<<<gout, 512, GEMM_SMEM>>>(bo, out);
}

// round 8
// speedup vs baseline: 3.3427x; 1.0406x over previous
#include <cuda_runtime.h>
#include <cuda_bf16.h>
#include <math.h>
#include <cstdint>

#define E_DIM 1024
#define M_DIM 4096
#define H_NUM 16
#define HD 64
#define B_SZ 4
#define NELEM (M_DIM * E_DIM)
#define WSZ (E_DIM * E_DIM)

// bf16 hi/lo split buffers (inputs to GEMMs)
__device__ __nv_bfloat16 in_q_h[NELEM], in_q_l[NELEM];
__device__ __nv_bfloat16 in_k_h[NELEM], in_k_l[NELEM];
__device__ __nv_bfloat16 in_v_h[NELEM], in_v_l[NELEM];
__device__ __nv_bfloat16 w_h[5 * WSZ],  w_l[5 * WSZ];

// proj outputs (bf16 hi/lo), attention output (bf16 hi/lo)
__device__ __nv_bfloat16 o_q_h[NELEM],  o_q_l[NELEM];
__device__ __nv_bfloat16 o_k1_h[NELEM], o_k1_l[NELEM];
__device__ __nv_bfloat16 o_k2_h[NELEM], o_k2_l[NELEM];
__device__ __nv_bfloat16 o_v_h[NELEM],  o_v_l[NELEM];
__device__ __nv_bfloat16 ao_h[NELEM],   ao_l[NELEM];

// norms: [bh*1024 + t]
__device__ float n_q2[64 * 1024];
__device__ float n_k1[64 * 1024];
__device__ float n_k2[64 * 1024];

// ===========================================================================
// helpers
// ===========================================================================
__device__ __forceinline__ uint32_t smem_u32(const void* p) {
    uint32_t a;
    asm("{ .reg .u64 t; cvta.to.shared.u64 t, %1; cvt.u32.u64 %0, t; }"
        : "=r"(a) : "l"(p));
    return a;
}
__device__ __forceinline__ void cp_async16(uint32_t dst, const void* src) {
    asm volatile("cp.async.cg.shared.global [%0], [%1], 16;"
                 :: "r"(dst), "l"(src));
}
__device__ __forceinline__ void cp_commit() {
    asm volatile("cp.async.commit_group;" ::: "memory");
}
__device__ __forceinline__ void cp_wait1() {
    asm volatile("cp.async.wait_group 1;" ::: "memory");
}
__device__ __forceinline__ void cp_wait0() {
    asm volatile("cp.async.wait_group 0;" ::: "memory");
}
__device__ __forceinline__ void ldsm4(uint32_t addr, uint32_t* r) {
    asm volatile("ldmatrix.sync.aligned.m8n8.x4.shared.b16 {%0,%1,%2,%3}, [%4];"
                 : "=r"(r[0]), "=r"(r[1]), "=r"(r[2]), "=r"(r[3]) : "r"(addr));
}
__device__ __forceinline__ void ldsm4t(uint32_t addr, uint32_t* r) {
    asm volatile("ldmatrix.sync.aligned.m8n8.x4.trans.shared.b16 {%0,%1,%2,%3}, [%4];"
                 : "=r"(r[0]), "=r"(r[1]), "=r"(r[2]), "=r"(r[3]) : "r"(addr));
}
__device__ __forceinline__ void mma16816(float* d, const uint32_t* a,
                                         const uint32_t* b) {
    asm volatile(
        "mma.sync.aligned.m16n8k16.row.col.f32.bf16.bf16.f32 "
        "{%0,%1,%2,%3}, {%4,%5,%6,%7}, {%8,%9}, {%0,%1,%2,%3};"
        : "+f"(d[0]), "+f"(d[1]), "+f"(d[2]), "+f"(d[3])
        : "r"(a[0]), "r"(a[1]), "r"(a[2]), "r"(a[3]), "r"(b[0]), "r"(b[1]));
}
__device__ __forceinline__ void split2(float x, float y, uint32_t& hi, uint32_t& lo) {
    __nv_bfloat162 h = __float22bfloat162_rn(make_float2(x, y));
    float2 f = __bfloat1622float2(h);
    __nv_bfloat162 l = __float22bfloat162_rn(make_float2(x - f.x, y - f.y));
    hi = *reinterpret_cast<uint32_t*>(&h);
    lo = *reinterpret_cast<uint32_t*>(&l);
}

// ===========================================================================
// fused fp32 -> bf16 hi/lo split for all 8 source tensors (one launch)
// grid = (4096, 8); weights use only 1024 x-blocks, rest early-exit
// ===========================================================================
extern "C" __global__ void __launch_bounds__(256)
split_all(const float* __restrict__ q, const float* __restrict__ k,
          const float* __restrict__ v, const float* __restrict__ wq,
          const float* __restrict__ wk1, const float* __restrict__ wk2,
          const float* __restrict__ wv, const float* __restrict__ wo) {
    const float* src;
    __nv_bfloat16 *hi, *lo;
    int n4;
    switch (blockIdx.y) {
        case 0: src = q;   hi = in_q_h; lo = in_q_l; n4 = NELEM / 4; break;
        case 1: src = k;   hi = in_k_h; lo = in_k_l; n4 = NELEM / 4; break;
        case 2: src = v;   hi = in_v_h; lo = in_v_l; n4 = NELEM / 4; break;
        case 3: src = wq;  hi = w_h + 0 * (size_t)WSZ; lo = w_l + 0 * (size_t)WSZ; n4 = WSZ / 4; break;
        case 4: src = wk1; hi = w_h + 1 * (size_t)WSZ; lo = w_l + 1 * (size_t)WSZ; n4 = WSZ / 4; break;
        case 5: src = wk2; hi = w_h + 2 * (size_t)WSZ; lo = w_l + 2 * (size_t)WSZ; n4 = WSZ / 4; break;
        case 6: src = wv;  hi = w_h + 3 * (size_t)WSZ; lo = w_l + 3 * (size_t)WSZ; n4 = WSZ / 4; break;
        default: src = wo; hi = w_h + 4 * (size_t)WSZ; lo = w_l + 4 * (size_t)WSZ; n4 = WSZ / 4; break;
    }
    int i = blockIdx.x * 256 + threadIdx.x;
    if (i >= n4) return;
    float4 val = ((const float4*)src)[i];
    uint32_t h0, l0, h1, l1;
    split2(val.x, val.y, h0, l0);
    split2(val.z, val.w, h1, l1);
    ((uint32_t*)hi)[i * 2]     = h0;
    ((uint32_t*)hi)[i * 2 + 1] = h1;
    ((uint32_t*)lo)[i * 2]     = l0;
    ((uint32_t*)lo)[i * 2 + 1] = l1;
}

// ===========================================================================
// mma.sync GEMM: C[M,N] = A[M,K] @ W[N,K]^T + bias  (bf16 hi/lo, fp32 acc)
// CTA 128x128, K chunk 64, 512 threads. Epilogue: fp32 OR bf16 hi/lo.
// ===========================================================================
#define GEMM_SMEM 131072

__device__ __forceinline__ void gemm_mma_body(
    const __nv_bfloat16* __restrict__ Ah, const __nv_bfloat16* __restrict__ Al,
    const __nv_bfloat16* __restrict__ Wh, const __nv_bfloat16* __restrict__ Wl,
    const float* __restrict__ bias, float* __restrict__ Cf,
    __nv_bfloat16* __restrict__ Ch, __nv_bfloat16* __restrict__ Cl) {
    extern __shared__ char smem[];
    const uint32_t sbase = smem_u32(smem);
    const int tid = threadIdx.x;
    const int lane = tid & 31;
    const int wid = tid >> 5;
    const int bm = blockIdx.y * 128;
    const int bn = blockIdx.x * 128;
    const int wm = (wid & 3) * 32;
    const int wn = (wid >> 2) * 32;

    const int lrow = tid >> 2;
    const int lc0 = (tid & 3) * 2;
    const size_t goffA = (size_t)(bm + lrow) * E_DIM;
    const size_t goffW = (size_t)(bn + lrow) * E_DIM;

    float acc[2][4][4];
#pragma unroll
    for (int mt = 0; mt < 2; mt++)
#pragma unroll
        for (int nt = 0; nt < 4; nt++)
#pragma unroll
            for (int e = 0; e < 4; e++) acc[mt][nt][e] = 0.0f;

#define LOAD_CHUNK(buf, kc) do {                                              \
    uint32_t dst0 = sbase + (buf) * 65536 + lrow * 128;                       \
    _Pragma("unroll")                                                         \
    for (int j = 0; j < 2; j++) {                                             \
        int c = lc0 + j;                                                      \
        uint32_t d = dst0 + (((c) ^ (lrow & 7)) << 4);                        \
        cp_async16(d,         Ah + goffA + (kc) + c * 8);                     \
        cp_async16(d + 16384, Al + goffA + (kc) + c * 8);                     \
        cp_async16(d + 32768, Wh + goffW + (kc) + c * 8);                     \
        cp_async16(d + 49152, Wl + goffW + (kc) + c * 8);                     \
    }                                                                         \
} while (0)

    LOAD_CHUNK(0, 0);
    cp_commit();

    const int nk = E_DIM / 64;
    for (int kc = 0; kc < nk; kc++) {
        if (kc + 1 < nk) {
            LOAD_CHUNK((kc + 1) & 1, (kc + 1) * 64);
            cp_commit();
            cp_wait1();
        } else {
            cp_wait0();
        }
        __syncthreads();

        const uint32_t tb = sbase + (kc & 1) * 65536;
#pragma unroll
        for (int s = 0; s < 4; s++) {
            uint32_t a_h[2][4], a_l[2][4];
            const int ac = s * 2 + (lane >> 4);
#pragma unroll
            for (int mt = 0; mt < 2; mt++) {
                int r = wm + mt * 16 + (lane & 15);
                uint32_t ad = tb + r * 128 + ((ac ^ (r & 7)) << 4);
                ldsm4(ad, a_h[mt]);
                ldsm4(ad + 16384, a_l[mt]);
            }
            uint32_t b_h[4][2], b_l[4][2];
            const int grp = lane >> 3;
            const int bc = s * 2 + (grp & 1);
            const int br = wn + ((grp >> 1) << 3) + (lane & 7);
#pragma unroll
            for (int np = 0; np < 2; np++) {
                int r = br + np * 16;
                uint32_t bd = tb + 32768 + r * 128 + ((bc ^ (r & 7)) << 4);
                uint32_t qv[4];
                ldsm4(bd, qv);
                b_h[np * 2][0] = qv[0]; b_h[np * 2][1] = qv[1];
                b_h[np * 2 + 1][0] = qv[2]; b_h[np * 2 + 1][1] = qv[3];
                ldsm4(bd + 16384, qv);
                b_l[np * 2][0] = qv[0]; b_l[np * 2][1] = qv[1];
                b_l[np * 2 + 1][0] = qv[2]; b_l[np * 2 + 1][1] = qv[3];
            }
#pragma unroll
            for (int mt = 0; mt < 2; mt++)
#pragma unroll
                for (int nt = 0; nt < 4; nt++) {
                    mma16816(acc[mt][nt], a_h[mt], b_h[nt]);
                    mma16816(acc[mt][nt], a_h[mt], b_l[nt]);
                    mma16816(acc[mt][nt], a_l[mt], b_h[nt]);
                }
        }
        __syncthreads();
    }
#undef LOAD_CHUNK

    // epilogue
#pragma unroll
    for (int mt = 0; mt < 2; mt++) {
        int r0 = bm + wm + mt * 16 + (lane >> 2);
#pragma unroll
        for (int nt = 0; nt < 4; nt++) {
            int cg = bn + wn + nt * 8 + ((lane & 3) << 1);
            float2 bb = *(const float2*)&bias[cg];
            float v00 = acc[mt][nt][0] + bb.x, v01 = acc[mt][nt][1] + bb.y;
            float v10 = acc[mt][nt][2] + bb.x, v11 = acc[mt][nt][3] + bb.y;
            if (Cf) {
                *(float2*)&Cf[(size_t)r0 * E_DIM + cg] = make_float2(v00, v01);
                *(float2*)&Cf[(size_t)(r0 + 8) * E_DIM + cg] = make_float2(v10, v11);
            } else {
                uint32_t h0, l0, h1, l1;
                split2(v00, v01, h0, l0);
                split2(v10, v11, h1, l1);
                *(uint32_t*)&Ch[(size_t)r0 * E_DIM + cg] = h0;
                *(uint32_t*)&Cl[(size_t)r0 * E_DIM + cg] = l0;
                *(uint32_t*)&Ch[(size_t)(r0 + 8) * E_DIM + cg] = h1;
                *(uint32_t*)&Cl[(size_t)(r0 + 8) * E_DIM + cg] = l1;
            }
        }
    }
}

// Fused 4-way projection: z=0:q z=1:k1 z=2:k2 z=3:v  -> bf16 hi/lo outputs
extern "C" __global__ void __launch_bounds__(512)
proj_kernel(const float* __restrict__ bias) {
    const __nv_bfloat16 *Ah, *Al;
    __nv_bfloat16 *Ch, *Cl;
    int z = blockIdx.z;
    if (z == 0)      { Ah = in_q_h; Al = in_q_l; Ch = o_q_h;  Cl = o_q_l;  }
    else if (z == 1) { Ah = in_k_h; Al = in_k_l; Ch = o_k1_h; Cl = o_k1_l; }
    else if (z == 2) { Ah = in_k_h; Al = in_k_l; Ch = o_k2_h; Cl = o_k2_l; }
    else             { Ah = in_v_h; Al = in_v_l; Ch = o_v_h;  Cl = o_v_l;  }
    gemm_mma_body(Ah, Al, w_h + (size_t)z * WSZ, w_l + (size_t)z * WSZ,
                  bias + z * E_DIM, nullptr, Ch, Cl);
}

extern "C" __global__ void __launch_bounds__(512)
out_kernel(const float* __restrict__ bias, float* __restrict__ C) {
    gemm_mma_body(ao_h, ao_l, w_h + (size_t)4 * WSZ, w_l + (size_t)4 * WSZ,
                  bias, C, nullptr, nullptr);
}

// ===========================================================================
// norm kernel: per-head squared norms of q, k1, k2 (from hi+lo)
// ===========================================================================
extern "C" __global__ void __launch_bounds__(256)
norm_kernel() {
    const int z = blockIdx.y;
    const __nv_bfloat16 *H, *L;
    float* N;
    if (z == 0)      { H = o_q_h;  L = o_q_l;  N = n_q2; }
    else if (z == 1) { H = o_k1_h; L = o_k1_l; N = n_k1; }
    else             { H = o_k2_h; L = o_k2_l; N = n_k2; }
    const int idx = blockIdx.x * 256 + threadIdx.x;      // 0..65535
    const int h = idx & 15, tb = idx >> 4;
    const size_t base = (size_t)tb * E_DIM + h * HD;
    float s = 0.0f;
#pragma unroll
    for (int g = 0; g < 8; g++) {
        uint4 uh = *(const uint4*)(H + base + g * 8);
        uint4 ul = *(const uint4*)(L + base + g * 8);
#define ACC2(uw, lw) { \
        float2 fa = __bfloat1622float2(*(__nv_bfloat162*)&(uw)); \
        float2 fc = __bfloat1622float2(*(__nv_bfloat162*)&(lw)); \
        float v0 = fa.x + fc.x, v1 = fa.y + fc.y; \
        s = fmaf(v0, v0, s); s = fmaf(v1, v1, s); }
        ACC2(uh.x, ul.x) ACC2(uh.y, ul.y) ACC2(uh.z, ul.z) ACC2(uh.w, ul.w)
#undef ACC2
    }
    N[(size_t)((tb & 3) * 16 + h) * 1024 + (tb >> 2)] = s;
}

// ===========================================================================
// Tensorized Gaussian-kernel attention, register-resident weights.
// Block = (64 q rows, bh), 256 threads = 8 warps (4 m-strips x 2 s-halves).
// Warp (wm, wn): QK over s in [wn*32, wn*32+32), AV partial over that s-half
// across ALL 64 output cols; O pair-reduced through smem at the end.
// ===========================================================================
#define AT_SQH 0
#define AT_SQL 8192
#define AT_Q2  16384
#define AT_DEN 16640
#define AT_ORED 17152
#define AT_BUF0 34560
#define AT_BUFSZ 49664
#define AT_K1H 0
#define AT_K1L 8192
#define AT_K2H 16384
#define AT_K2L 24576
#define AT_VH  32768
#define AT_VL  40960
#define AT_N1  49152
#define AT_N2  49408
#define ATTN_SMEM (AT_BUF0 + 2 * AT_BUFSZ)

extern "C" __global__ void __launch_bounds__(256)
attn_kernel(const float* __restrict__ pi) {
    extern __shared__ char smem[];
    const uint32_t sb = smem_u32(smem);
    const int tid = threadIdx.x;
    const int lane = tid & 31;
    const int wid = tid >> 5;
    const int wm = (wid & 3) * 16;
    const int wn = wid >> 2;
    const int qt = blockIdx.x;
    const int bh = blockIdx.y;
    const int b = bh >> 4;
    const int h = bh & 15;
    const int q0 = qt * 64;

    const float p1 = fminf(fmaxf(fabsf(pi[h]), 1e-6f), 2.0f);
    const float p2 = fminf(fmaxf(fabsf(pi[H_NUM + h]), 1e-6f), 2.0f);

    const int lr = tid >> 2;
    const int lc = (tid & 3) * 2;
    const size_t grow = (size_t)h * HD;

#define LOADKV(buf, s0) do {                                                      \
    uint32_t bdst = sb + AT_BUF0 + (buf) * AT_BUFSZ;                              \
    size_t gsrc = ((size_t)((s0) + lr) * B_SZ + b) * E_DIM + grow;                \
    _Pragma("unroll")                                                             \
    for (int j = 0; j < 2; j++) {                                                 \
        int c = lc + j;                                                           \
        uint32_t d = bdst + lr * 128 + ((c ^ (lr & 7)) << 4);                     \
        cp_async16(d + AT_K1H, o_k1_h + gsrc + c * 8);                            \
        cp_async16(d + AT_K1L, o_k1_l + gsrc + c * 8);                            \
        cp_async16(d + AT_K2H, o_k2_h + gsrc + c * 8);                            \
        cp_async16(d + AT_K2L, o_k2_l + gsrc + c * 8);                            \
        cp_async16(d + AT_VH,  o_v_h  + gsrc + c * 8);                            \
        cp_async16(d + AT_VL,  o_v_l  + gsrc + c * 8);                            \
    }                                                                             \
    if (tid < 16)                                                                 \
        cp_async16(bdst + AT_N1 + tid * 16, n_k1 + (size_t)bh * 1024 + (s0) + tid * 4); \
    else if (tid < 32)                                                            \
        cp_async16(bdst + AT_N2 + (tid - 16) * 16, n_k2 + (size_t)bh * 1024 + (s0) + (tid - 16) * 4); \
} while (0)

    // Q tiles + q2 + first KV buffer in one group
    {
        size_t g = ((size_t)(q0 + lr) * B_SZ + b) * E_DIM + grow;
#pragma unroll
        for (int j = 0; j < 2; j++) {
            int c = lc + j;
            uint32_t sw = (uint32_t)((c ^ (lr & 7)) << 4);
            cp_async16(sb + AT_SQH + lr * 128 + sw, o_q_h + g + c * 8);
            cp_async16(sb + AT_SQL + lr * 128 + sw, o_q_l + g + c * 8);
        }
        if (tid < 16)
            cp_async16(sb + AT_Q2 + tid * 16, n_q2 + (size_t)bh * 1024 + q0 + tid * 4);
    }
    LOADKV(0, 0);
    cp_commit();

    float O[8][4];
#pragma unroll
    for (int nt = 0; nt < 8; nt++)
#pragma unroll
        for (int e = 0; e < 4; e++) O[nt][e] = 0.0f;
    float den0 = 0.0f, den1 = 0.0f;

    for (int st = 0; st < 16; st++) {
        cp_wait0();
        __syncthreads();
        if (st < 15) { LOADKV((st + 1) & 1, (st + 1) * 64); cp_commit(); }

        const uint32_t bb = sb + AT_BUF0 + (st & 1) * AT_BUFSZ;
        char* bbp = smem + AT_BUF0 + (st & 1) * AT_BUFSZ;

        float S1[4][4], S2[4][4];
#pragma unroll
        for (int nt = 0; nt < 4; nt++)
#pragma unroll
            for (int e = 0; e < 4; e++) { S1[nt][e] = 0.0f; S2[nt][e] = 0.0f; }

        // ---- QK: S over this warp's 32-key half ----
#pragma unroll
        for (int kk = 0; kk < 4; kk++) {
            uint32_t ah[4], al[4];
            {
                int r = wm + (lane & 15);
                int c = kk * 2 + (lane >> 4);
                uint32_t ad = sb + AT_SQH + r * 128 + ((c ^ (r & 7)) << 4);
                ldsm4(ad, ah);
                ldsm4(ad + 8192, al);
            }
            uint32_t b1h[4][2], b1l[4][2], b2h[4][2], b2l[4][2];
            {
                const int grp = lane >> 3;
                const int c = kk * 2 + (grp & 1);
                const int rb = wn * 32 + ((grp >> 1) << 3) + (lane & 7);
#pragma unroll
                for (int np = 0; np < 2; np++) {
                    int r = rb + np * 16;
                    uint32_t ra = bb + r * 128 + ((c ^ (r & 7)) << 4);
                    uint32_t qv[4];
                    ldsm4(ra + AT_K1H, qv);
                    b1h[np*2][0]=qv[0]; b1h[np*2][1]=qv[1]; b1h[np*2+1][0]=qv[2]; b1h[np*2+1][1]=qv[3];
                    ldsm4(ra + AT_K1L, qv);
                    b1l[np*2][0]=qv[0]; b1l[np*2][1]=qv[1]; b1l[np*2+1][0]=qv[2]; b1l[np*2+1][1]=qv[3];
                    ldsm4(ra + AT_K2H, qv);
                    b2h[np*2][0]=qv[0]; b2h[np*2][1]=qv[1]; b2h[np*2+1][0]=qv[2]; b2h[np*2+1][1]=qv[3];
                    ldsm4(ra + AT_K2L, qv);
                    b2l[np*2][0]=qv[0]; b2l[np*2][1]=qv[1]; b2l[np*2+1][0]=qv[2]; b2l[np*2+1][1]=qv[3];
                }
            }
#pragma unroll
            for (int nt = 0; nt < 4; nt++) {
                mma16816(S1[nt], ah, b1h[nt]);
                mma16816(S1[nt], ah, b1l[nt]);
                mma16816(S1[nt], al, b1h[nt]);
                mma16816(S2[nt], ah, b2h[nt]);
                mma16816(S2[nt], ah, b2l[nt]);
                mma16816(S2[nt], al, b2h[nt]);
            }
        }

        // ---- weights in registers: w = p1 e1 + p2 e2; pack to A-frags ----
        uint32_t wAh[2][4], wAl[2][4];
        {
            const int r0 = wm + (lane >> 2);
            const float q2a = *(const float*)(smem + AT_Q2 + r0 * 4);
            const float q2b = *(const float*)(smem + AT_Q2 + (r0 + 8) * 4);
            const float* k1p = (const float*)(bbp + AT_N1);
            const float* k2p = (const float*)(bbp + AT_N2);
#pragma unroll
            for (int nt = 0; nt < 4; nt++) {
                const int cp0 = wn * 32 + nt * 8 + 2 * (lane & 3);
                const float k1a = k1p[cp0], k1b = k1p[cp0 + 1];
                const float k2a = k2p[cp0], k2b = k2p[cp0 + 1];
                float w00 = p1 * __expf(-0.0625f * (q2a + k1a - 2.0f * S1[nt][0]))
                          + p2 * __expf(-0.1875f * (q2a + k2a - 2.0f * S2[nt][0]));
                float w01 = p1 * __expf(-0.0625f * (q2a + k1b - 2.0f * S1[nt][1]))
                          + p2 * __expf(-0.1875f * (q2a + k2b - 2.0f * S2[nt][1]));
                float w10 = p1 * __expf(-0.0625f * (q2b + k1a - 2.0f * S1[nt][2]))
                          + p2 * __expf(-0.1875f * (q2b + k2a - 2.0f * S2[nt][2]));
                float w11 = p1 * __expf(-0.0625f * (q2b + k1b - 2.0f * S1[nt][3]))
                          + p2 * __expf(-0.1875f * (q2b + k2b - 2.0f * S2[nt][3]));
                den0 += w00 + w01;
                den1 += w10 + w11;
                // C-frag (two adjacent n8 tiles) == A-frag of m16k16:
                // a0=(g,k2j) from even tile, a1=(g+8,k2j), a2/a3 = odd tile
                uint32_t h0, l0, h1, l1;
                split2(w00, w01, h0, l0);
                split2(w10, w11, h1, l1);
                const int kk = nt >> 1;
                const int e = (nt & 1) * 2;
                wAh[kk][e]     = h0; wAl[kk][e]     = l0;
                wAh[kk][e + 1] = h1; wAl[kk][e + 1] = l1;
            }
        }

        // ---- AV: O(partial over s-half) += w @ V, all 64 cols ----
#pragma unroll
        for (int kk = 0; kk < 2; kk++) {
            uint32_t bvh[8][2], bvl[8][2];
            {
                int r = wn * 32 + kk * 16 + (lane & 15);
                uint32_t rowa = bb + AT_VH + r * 128;
                uint32_t rowb = bb + AT_VL + r * 128;
#pragma unroll
                for (int cb = 0; cb < 8; cb += 2) {
                    int g0 = cb + (lane >> 4);
                    uint32_t qv[4];
                    ldsm4t(rowa + ((g0 ^ (r & 7)) << 4), qv);
                    bvh[cb][0]=qv[0]; bvh[cb][1]=qv[1]; bvh[cb+1][0]=qv[2]; bvh[cb+1][1]=qv[3];
                    ldsm4t(rowb + ((g0 ^ (r & 7)) << 4), qv);
                    bvl[cb][0]=qv[0]; bvl[cb][1]=qv[1]; bvl[cb+1][0]=qv[2]; bvl[cb+1][1]=qv[3];
                }
            }
#pragma unroll
            for (int nt = 0; nt < 8; nt++) {
                mma16816(O[nt], wAh[kk], bvh[nt]);
                mma16816(O[nt], wAh[kk], bvl[nt]);
                mma16816(O[nt], wAl[kk], bvh[nt]);
            }
        }
    }
#undef LOADKV

    // ---- cross-warp reduction of O and den over the two s-halves ----
    den0 += __shfl_xor_sync(0xffffffffu, den0, 1);
    den0 += __shfl_xor_sync(0xffffffffu, den0, 2);
    den1 += __shfl_xor_sync(0xffffffffu, den1, 1);
    den1 += __shfl_xor_sync(0xffffffffu, den1, 2);

    float* dens = (float*)(smem + AT_DEN);
    float* ored = (float*)(smem + AT_ORED);
    const int r0 = wm + (lane >> 2);
    __syncthreads();
    if ((lane & 3) == 0) {
        dens[r0 * 2 + wn] = den0;
        dens[(r0 + 8) * 2 + wn] = den1;
    }
    if (wn == 1) {
#pragma unroll
        for (int nt = 0; nt < 8; nt++) {
            const int c = nt * 8 + 2 * (lane & 3);
            *(float2*)&ored[r0 * 68 + c] = make_float2(O[nt][0], O[nt][1]);
            *(float2*)&ored[(r0 + 8) * 68 + c] = make_float2(O[nt][2], O[nt][3]);
        }
    }
    __syncthreads();
    if (wn == 0) {
        const float ia = 1.0f / (dens[r0 * 2] + dens[r0 * 2 + 1] + 1e-6f);
        const float ib = 1.0f / (dens[(r0 + 8) * 2] + dens[(r0 + 8) * 2 + 1] + 1e-6f);
#pragma unroll
        for (int nt = 0; nt < 8; nt++) {
            const int c = nt * 8 + 2 * (lane & 3);
            float2 pa = *(const float2*)&ored[r0 * 68 + c];
            float2 pb = *(const float2*)&ored[(r0 + 8) * 68 + c];
            float o00 = (O[nt][0] + pa.x) * ia, o01 = (O[nt][1] + pa.y) * ia;
            float o10 = (O[nt][2] + pb.x) * ib, o11 = (O[nt][3] + pb.y) * ib;
            uint32_t h0, l0, h1, l1;
            split2(o00, o01, h0, l0);
            split2(o10, o11, h1, l1);
            size_t i0 = ((size_t)(q0 + r0) * B_SZ + b) * E_DIM + grow + c;
            size_t i1 = i0 + (size_t)8 * B_SZ * E_DIM;
            *(uint32_t*)&ao_h[i0] = h0; *(uint32_t*)&ao_l[i0] = l0;
            *(uint32_t*)&ao_h[i1] = h1; *(uint32_t*)&ao_l[i1] = l1;
        }
    }
}

// ---------------------------------------------------------------------------
extern "C" void kernel_launch(void* const* d_in, const int* in_sizes, int n_in,
                              void* d_out, int out_size) {
    const float* query = (const float*)d_in[0];
    const float* key   = (const float*)d_in[1];
    const float* value = (const float*)d_in[2];
    const float* wq    = (const float*)d_in[3];
    const float* wk1   = (const float*)d_in[4];
    const float* wk2   = (const float*)d_in[5];
    const float* wv    = (const float*)d_in[6];
    const float* bias  = (const float*)d_in[7];
    const float* wo    = (const float*)d_in[8];
    const float* bo    = (const float*)d_in[9];
    const float* pi    = (const float*)d_in[10];
    float* out = (float*)d_out;

    cudaFuncSetAttribute(proj_kernel,
                         cudaFuncAttributeMaxDynamicSharedMemorySize, GEMM_SMEM);
    cudaFuncSetAttribute(out_kernel,
                         cudaFuncAttributeMaxDynamicSharedMemorySize, GEMM_SMEM);
    cudaFuncSetAttribute(attn_kernel,
                         cudaFuncAttributeMaxDynamicSharedMemorySize, ATTN_SMEM);

    dim3 gsplit(4096, 8);
    split_all<<<gsplit, 256>>>(query, key, value, wq, wk1, wk2, wv, wo);

    dim3 gproj(8, 32, 4);
    proj_kernel<<<gproj, 512, GEMM_SMEM>>>(bias);

    dim3 gnorm(256, 3);
    norm_kernel<<<gnorm, 256>>>();

    dim3 gattn(16, 64);
    attn_kernel<<<gattn, 256, ATTN_SMEM>>>(pi);

    dim3 gout(8, 32);
    out_kernel<<<gout, 512, GEMM_SMEM>>>(bo, out);
}

// round 11
// speedup vs baseline: 3.3512x; 1.0026x over previous
#include <cuda_runtime.h>
#include <cuda_bf16.h>
#include <math.h>
#include <cstdint>

#define E_DIM 1024
#define M_DIM 4096
#define H_NUM 16
#define HD 64
#define B_SZ 4
#define NELEM (M_DIM * E_DIM)
#define WSZ (E_DIM * E_DIM)

// bf16 hi/lo split buffers (inputs to GEMMs)
__device__ __nv_bfloat16 in_q_h[NELEM], in_q_l[NELEM];
__device__ __nv_bfloat16 in_k_h[NELEM], in_k_l[NELEM];
__device__ __nv_bfloat16 in_v_h[NELEM], in_v_l[NELEM];
__device__ __nv_bfloat16 w_h[5 * WSZ],  w_l[5 * WSZ];

// proj outputs (bf16 hi/lo), attention output (bf16 hi/lo)
__device__ __nv_bfloat16 o_q_h[NELEM],  o_q_l[NELEM];
__device__ __nv_bfloat16 o_k1_h[NELEM], o_k1_l[NELEM];
__device__ __nv_bfloat16 o_k2_h[NELEM], o_k2_l[NELEM];
__device__ __nv_bfloat16 o_v_h[NELEM],  o_v_l[NELEM];
__device__ __nv_bfloat16 ao_h[NELEM],   ao_l[NELEM];

// norms: [bh*1024 + t]
__device__ float n_q2[64 * 1024];
__device__ float n_k1[64 * 1024];
__device__ float n_k2[64 * 1024];

// ===========================================================================
// helpers
// ===========================================================================
__device__ __forceinline__ uint32_t smem_u32(const void* p) {
    uint32_t a;
    asm("{ .reg .u64 t; cvta.to.shared.u64 t, %1; cvt.u32.u64 %0, t; }"
        : "=r"(a) : "l"(p));
    return a;
}
__device__ __forceinline__ void cp_async16(uint32_t dst, const void* src) {
    asm volatile("cp.async.cg.shared.global [%0], [%1], 16;"
                 :: "r"(dst), "l"(src));
}
__device__ __forceinline__ void cp_commit() {
    asm volatile("cp.async.commit_group;" ::: "memory");
}
__device__ __forceinline__ void cp_wait1() {
    asm volatile("cp.async.wait_group 1;" ::: "memory");
}
__device__ __forceinline__ void cp_wait0() {
    asm volatile("cp.async.wait_group 0;" ::: "memory");
}
__device__ __forceinline__ void ldsm4(uint32_t addr, uint32_t* r) {
    asm volatile("ldmatrix.sync.aligned.m8n8.x4.shared.b16 {%0,%1,%2,%3}, [%4];"
                 : "=r"(r[0]), "=r"(r[1]), "=r"(r[2]), "=r"(r[3]) : "r"(addr));
}
__device__ __forceinline__ void ldsm4t(uint32_t addr, uint32_t* r) {
    asm volatile("ldmatrix.sync.aligned.m8n8.x4.trans.shared.b16 {%0,%1,%2,%3}, [%4];"
                 : "=r"(r[0]), "=r"(r[1]), "=r"(r[2]), "=r"(r[3]) : "r"(addr));
}
__device__ __forceinline__ void mma16816(float* d, const uint32_t* a,
                                         const uint32_t* b) {
    asm volatile(
        "mma.sync.aligned.m16n8k16.row.col.f32.bf16.bf16.f32 "
        "{%0,%1,%2,%3}, {%4,%5,%6,%7}, {%8,%9}, {%0,%1,%2,%3};"
        : "+f"(d[0]), "+f"(d[1]), "+f"(d[2]), "+f"(d[3])
        : "r"(a[0]), "r"(a[1]), "r"(a[2]), "r"(a[3]), "r"(b[0]), "r"(b[1]));
}
__device__ __forceinline__ void split2(float x, float y, uint32_t& hi, uint32_t& lo) {
    __nv_bfloat162 h = __float22bfloat162_rn(make_float2(x, y));
    float2 f = __bfloat1622float2(h);
    __nv_bfloat162 l = __float22bfloat162_rn(make_float2(x - f.x, y - f.y));
    hi = *reinterpret_cast<uint32_t*>(&h);
    lo = *reinterpret_cast<uint32_t*>(&l);
}

// ===========================================================================
// fused fp32 -> bf16 hi/lo split for all 8 source tensors (one launch)
// ===========================================================================
extern "C" __global__ void __launch_bounds__(256)
split_all(const float* __restrict__ q, const float* __restrict__ k,
          const float* __restrict__ v, const float* __restrict__ wq,
          const float* __restrict__ wk1, const float* __restrict__ wk2,
          const float* __restrict__ wv, const float* __restrict__ wo) {
    const float* src;
    __nv_bfloat16 *hi, *lo;
    int n4;
    switch (blockIdx.y) {
        case 0: src = q;   hi = in_q_h; lo = in_q_l; n4 = NELEM / 4; break;
        case 1: src = k;   hi = in_k_h; lo = in_k_l; n4 = NELEM / 4; break;
        case 2: src = v;   hi = in_v_h; lo = in_v_l; n4 = NELEM / 4; break;
        case 3: src = wq;  hi = w_h + 0 * (size_t)WSZ; lo = w_l + 0 * (size_t)WSZ; n4 = WSZ / 4; break;
        case 4: src = wk1; hi = w_h + 1 * (size_t)WSZ; lo = w_l + 1 * (size_t)WSZ; n4 = WSZ / 4; break;
        case 5: src = wk2; hi = w_h + 2 * (size_t)WSZ; lo = w_l + 2 * (size_t)WSZ; n4 = WSZ / 4; break;
        case 6: src = wv;  hi = w_h + 3 * (size_t)WSZ; lo = w_l + 3 * (size_t)WSZ; n4 = WSZ / 4; break;
        default: src = wo; hi = w_h + 4 * (size_t)WSZ; lo = w_l + 4 * (size_t)WSZ; n4 = WSZ / 4; break;
    }
    int i = blockIdx.x * 256 + threadIdx.x;
    if (i >= n4) return;
    float4 val = ((const float4*)src)[i];
    uint32_t h0, l0, h1, l1;
    split2(val.x, val.y, h0, l0);
    split2(val.z, val.w, h1, l1);
    ((uint32_t*)hi)[i * 2]     = h0;
    ((uint32_t*)hi)[i * 2 + 1] = h1;
    ((uint32_t*)lo)[i * 2]     = l0;
    ((uint32_t*)lo)[i * 2 + 1] = l1;
}

// ===========================================================================
// mma.sync GEMM: C[M,N] = A[M,K] @ W[N,K]^T + bias  (bf16 hi/lo, fp32 acc)
// CTA 128x128, K chunk 32, 256 threads (8 warps, 4m x 2n, warp tile 32x64).
// 2-stage smem: per stage Ah|Al|Wh|Wl each 8KB = 32KB; total 64KB => 2 CTA/SM.
// Row pitch 64B; swizzle granule g' = g ^ ((row>>1)&3).
// ===========================================================================
#define GEMM_SMEM 65536

__device__ __forceinline__ void gemm_mma_body(
    const __nv_bfloat16* __restrict__ Ah, const __nv_bfloat16* __restrict__ Al,
    const __nv_bfloat16* __restrict__ Wh, const __nv_bfloat16* __restrict__ Wl,
    const float* __restrict__ bias, float* __restrict__ Cf,
    __nv_bfloat16* __restrict__ Ch, __nv_bfloat16* __restrict__ Cl) {
    extern __shared__ char smem[];
    const uint32_t sbase = smem_u32(smem);
    const int tid = threadIdx.x;
    const int lane = tid & 31;
    const int wid = tid >> 5;
    const int bm = blockIdx.y * 128;
    const int bn = blockIdx.x * 128;
    const int wm = (wid & 3) * 32;
    const int wn = (wid >> 2) * 64;

    const int lr = tid >> 1;            // 0..127
    const int lg = (tid & 1) * 2;       // granule 0 or 2
    const size_t goffA = (size_t)(bm + lr) * E_DIM;
    const size_t goffW = (size_t)(bn + lr) * E_DIM;

    float acc[2][8][4];
#pragma unroll
    for (int mt = 0; mt < 2; mt++)
#pragma unroll
        for (int nt = 0; nt < 8; nt++)
#pragma unroll
            for (int e = 0; e < 4; e++) acc[mt][nt][e] = 0.0f;

#define LOAD_CHUNK(buf, kc) do {                                              \
    uint32_t dst0 = sbase + (buf) * 32768 + lr * 64;                          \
    _Pragma("unroll")                                                         \
    for (int j = 0; j < 2; j++) {                                             \
        int g = lg + j;                                                       \
        uint32_t d = dst0 + (((g) ^ ((lr >> 1) & 3)) << 4);                   \
        cp_async16(d,         Ah + goffA + (kc) + g * 8);                     \
        cp_async16(d + 8192,  Al + goffA + (kc) + g * 8);                     \
        cp_async16(d + 16384, Wh + goffW + (kc) + g * 8);                     \
        cp_async16(d + 24576, Wl + goffW + (kc) + g * 8);                     \
    }                                                                         \
} while (0)

    LOAD_CHUNK(0, 0);
    cp_commit();

    const int nk = E_DIM / 32;
    for (int kc = 0; kc < nk; kc++) {
        if (kc + 1 < nk) {
            LOAD_CHUNK((kc + 1) & 1, (kc + 1) * 32);
            cp_commit();
            cp_wait1();
        } else {
            cp_wait0();
        }
        __syncthreads();

        const uint32_t tb = sbase + (kc & 1) * 32768;
#pragma unroll
        for (int s = 0; s < 2; s++) {
            uint32_t a_h[2][4], a_l[2][4];
            const int ac = s * 2 + (lane >> 4);
#pragma unroll
            for (int mt = 0; mt < 2; mt++) {
                int r = wm + mt * 16 + (lane & 15);
                uint32_t ad = tb + r * 64 + ((ac ^ ((r >> 1) & 3)) << 4);
                ldsm4(ad, a_h[mt]);
                ldsm4(ad + 8192, a_l[mt]);
            }
            uint32_t b_h[8][2], b_l[8][2];
            const int grp = lane >> 3;
            const int bc = s * 2 + (grp & 1);
            const int br = wn + ((grp >> 1) << 3) + (lane & 7);
#pragma unroll
            for (int np = 0; np < 4; np++) {
                int r = br + np * 16;
                uint32_t bd = tb + 16384 + r * 64 + ((bc ^ ((r >> 1) & 3)) << 4);
                uint32_t qv[4];
                ldsm4(bd, qv);
                b_h[np * 2][0] = qv[0]; b_h[np * 2][1] = qv[1];
                b_h[np * 2 + 1][0] = qv[2]; b_h[np * 2 + 1][1] = qv[3];
                ldsm4(bd + 8192, qv);
                b_l[np * 2][0] = qv[0]; b_l[np * 2][1] = qv[1];
                b_l[np * 2 + 1][0] = qv[2]; b_l[np * 2 + 1][1] = qv[3];
            }
#pragma unroll
            for (int mt = 0; mt < 2; mt++)
#pragma unroll
                for (int nt = 0; nt < 8; nt++) {
                    mma16816(acc[mt][nt], a_h[mt], b_h[nt]);
                    mma16816(acc[mt][nt], a_h[mt], b_l[nt]);
                    mma16816(acc[mt][nt], a_l[mt], b_h[nt]);
                }
        }
        __syncthreads();
    }
#undef LOAD_CHUNK

    // epilogue
#pragma unroll
    for (int mt = 0; mt < 2; mt++) {
        int r0 = bm + wm + mt * 16 + (lane >> 2);
#pragma unroll
        for (int nt = 0; nt < 8; nt++) {
            int cg = bn + wn + nt * 8 + ((lane & 3) << 1);
            float2 bb = *(const float2*)&bias[cg];
            float v00 = acc[mt][nt][0] + bb.x, v01 = acc[mt][nt][1] + bb.y;
            float v10 = acc[mt][nt][2] + bb.x, v11 = acc[mt][nt][3] + bb.y;
            if (Cf) {
                *(float2*)&Cf[(size_t)r0 * E_DIM + cg] = make_float2(v00, v01);
                *(float2*)&Cf[(size_t)(r0 + 8) * E_DIM + cg] = make_float2(v10, v11);
            } else {
                uint32_t h0, l0, h1, l1;
                split2(v00, v01, h0, l0);
                split2(v10, v11, h1, l1);
                *(uint32_t*)&Ch[(size_t)r0 * E_DIM + cg] = h0;
                *(uint32_t*)&Cl[(size_t)r0 * E_DIM + cg] = l0;
                *(uint32_t*)&Ch[(size_t)(r0 + 8) * E_DIM + cg] = h1;
                *(uint32_t*)&Cl[(size_t)(r0 + 8) * E_DIM + cg] = l1;
            }
        }
    }
}

// Fused 4-way projection: z=0:q z=1:k1 z=2:k2 z=3:v  -> bf16 hi/lo outputs
extern "C" __global__ void __launch_bounds__(256, 2)
proj_kernel(const float* __restrict__ bias) {
    const __nv_bfloat16 *Ah, *Al;
    __nv_bfloat16 *Ch, *Cl;
    int z = blockIdx.z;
    if (z == 0)      { Ah = in_q_h; Al = in_q_l; Ch = o_q_h;  Cl = o_q_l;  }
    else if (z == 1) { Ah = in_k_h; Al = in_k_l; Ch = o_k1_h; Cl = o_k1_l; }
    else if (z == 2) { Ah = in_k_h; Al = in_k_l; Ch = o_k2_h; Cl = o_k2_l; }
    else             { Ah = in_v_h; Al = in_v_l; Ch = o_v_h;  Cl = o_v_l;  }
    gemm_mma_body(Ah, Al, w_h + (size_t)z * WSZ, w_l + (size_t)z * WSZ,
                  bias + z * E_DIM, nullptr, Ch, Cl);
}

extern "C" __global__ void __launch_bounds__(256, 2)
out_kernel(const float* __restrict__ bias, float* __restrict__ C) {
    gemm_mma_body(ao_h, ao_l, w_h + (size_t)4 * WSZ, w_l + (size_t)4 * WSZ,
                  bias, C, nullptr, nullptr);
}

// ===========================================================================
// norm kernel: per-head squared norms of q, k1, k2 (from hi+lo)
// ===========================================================================
extern "C" __global__ void __launch_bounds__(256)
norm_kernel() {
    const int z = blockIdx.y;
    const __nv_bfloat16 *H, *L;
    float* N;
    if (z == 0)      { H = o_q_h;  L = o_q_l;  N = n_q2; }
    else if (z == 1) { H = o_k1_h; L = o_k1_l; N = n_k1; }
    else             { H = o_k2_h; L = o_k2_l; N = n_k2; }
    const int idx = blockIdx.x * 256 + threadIdx.x;      // 0..65535
    const int h = idx & 15, tb = idx >> 4;
    const size_t base = (size_t)tb * E_DIM + h * HD;
    float s = 0.0f;
#pragma unroll
    for (int g = 0; g < 8; g++) {
        uint4 uh = *(const uint4*)(H + base + g * 8);
        uint4 ul = *(const uint4*)(L + base + g * 8);
#define ACC2(uw, lw) { \
        float2 fa = __bfloat1622float2(*(__nv_bfloat162*)&(uw)); \
        float2 fc = __bfloat1622float2(*(__nv_bfloat162*)&(lw)); \
        float v0 = fa.x + fc.x, v1 = fa.y + fc.y; \
        s = fmaf(v0, v0, s); s = fmaf(v1, v1, s); }
        ACC2(uh.x, ul.x) ACC2(uh.y, ul.y) ACC2(uh.z, ul.z) ACC2(uh.w, ul.w)
#undef ACC2
    }
    N[(size_t)((tb & 3) * 16 + h) * 1024 + (tb >> 2)] = s;
}

// ===========================================================================
// Tensorized Gaussian-kernel attention; Q frags + q2 in registers.
// Block = (64 q rows, bh), 256 threads = 8 warps (4 m-strips x 2 s-halves).
// smem = end-reduction scratch (8.7KB) + den + norms + 2x48KB KV => 2 CTA/SM.
// ===========================================================================
#define AT_ORED 0
#define AT_DEN  8704
#define AT_N    9216
#define AT_BUF0 10240
#define AT_BUFSZ 49152
#define AT_K1H 0
#define AT_K1L 8192
#define AT_K2H 16384
#define AT_K2L 24576
#define AT_VH  32768
#define AT_VL  40960
#define ATTN_SMEM (AT_BUF0 + 2 * AT_BUFSZ)

extern "C" __global__ void __launch_bounds__(256, 2)
attn_kernel(const float* __restrict__ pi) {
    extern __shared__ char smem[];
    const uint32_t sb = smem_u32(smem);
    const int tid = threadIdx.x;
    const int lane = tid & 31;
    const int wid = tid >> 5;
    const int wm = (wid & 3) * 16;
    const int wn = wid >> 2;
    const int qt = blockIdx.x;
    const int bh = blockIdx.y;
    const int b = bh >> 4;
    const int h = bh & 15;
    const int q0 = qt * 64;

    const float p1 = fminf(fmaxf(fabsf(pi[h]), 1e-6f), 2.0f);
    const float p2 = fminf(fmaxf(fabsf(pi[H_NUM + h]), 1e-6f), 2.0f);

    const int lr = tid >> 2;
    const int lc = (tid & 3) * 2;
    const size_t grow = (size_t)h * HD;

#define LOADKV(buf, s0) do {                                                      \
    uint32_t bdst = sb + AT_BUF0 + (buf) * AT_BUFSZ;                              \
    size_t gsrc = ((size_t)((s0) + lr) * B_SZ + b) * E_DIM + grow;                \
    _Pragma("unroll")                                                             \
    for (int j = 0; j < 2; j++) {                                                 \
        int c = lc + j;                                                           \
        uint32_t d = bdst + lr * 128 + ((c ^ (lr & 7)) << 4);                     \
        cp_async16(d + AT_K1H, o_k1_h + gsrc + c * 8);                            \
        cp_async16(d + AT_K1L, o_k1_l + gsrc + c * 8);                            \
        cp_async16(d + AT_K2H, o_k2_h + gsrc + c * 8);                            \
        cp_async16(d + AT_K2L, o_k2_l + gsrc + c * 8);                            \
        cp_async16(d + AT_VH,  o_v_h  + gsrc + c * 8);                            \
        cp_async16(d + AT_VL,  o_v_l  + gsrc + c * 8);                            \
    }                                                                             \
    if (tid < 16)                                                                 \
        cp_async16(sb + AT_N + (buf) * 512 + tid * 16,                            \
                   n_k1 + (size_t)bh * 1024 + (s0) + tid * 4);                    \
    else if (tid < 32)                                                            \
        cp_async16(sb + AT_N + (buf) * 512 + 256 + (tid - 16) * 16,               \
                   n_k2 + (size_t)bh * 1024 + (s0) + (tid - 16) * 4);             \
} while (0)

    // ---- Q fragments + q2 straight into registers ----
    uint32_t qfh[4][4], qfl[4][4];
    {
        const int ra = q0 + wm + (lane >> 2);
        const size_t qa = ((size_t)ra * B_SZ + b) * E_DIM + grow;
        const size_t qb = qa + (size_t)8 * B_SZ * E_DIM;
#pragma unroll
        for (int kk = 0; kk < 4; kk++) {
            const int c0 = kk * 16 + 2 * (lane & 3);
            qfh[kk][0] = *(const uint32_t*)&o_q_h[qa + c0];
            qfh[kk][1] = *(const uint32_t*)&o_q_h[qb + c0];
            qfh[kk][2] = *(const uint32_t*)&o_q_h[qa + c0 + 8];
            qfh[kk][3] = *(const uint32_t*)&o_q_h[qb + c0 + 8];
            qfl[kk][0] = *(const uint32_t*)&o_q_l[qa + c0];
            qfl[kk][1] = *(const uint32_t*)&o_q_l[qb + c0];
            qfl[kk][2] = *(const uint32_t*)&o_q_l[qa + c0 + 8];
            qfl[kk][3] = *(const uint32_t*)&o_q_l[qb + c0 + 8];
        }
    }
    const float q2a = n_q2[(size_t)bh * 1024 + q0 + wm + (lane >> 2)];
    const float q2b = n_q2[(size_t)bh * 1024 + q0 + wm + (lane >> 2) + 8];

    LOADKV(0, 0);
    cp_commit();

    float O[8][4];
#pragma unroll
    for (int nt = 0; nt < 8; nt++)
#pragma unroll
        for (int e = 0; e < 4; e++) O[nt][e] = 0.0f;
    float den0 = 0.0f, den1 = 0.0f;

    for (int st = 0; st < 16; st++) {
        cp_wait0();
        __syncthreads();
        if (st < 15) { LOADKV((st + 1) & 1, (st + 1) * 64); cp_commit(); }

        const uint32_t bb = sb + AT_BUF0 + (st & 1) * AT_BUFSZ;

        float S1[4][4], S2[4][4];
#pragma unroll
        for (int nt = 0; nt < 4; nt++)
#pragma unroll
            for (int e = 0; e < 4; e++) { S1[nt][e] = 0.0f; S2[nt][e] = 0.0f; }

        // ---- QK over this warp's 32-key half (k1 then k2) ----
#pragma unroll
        for (int kk = 0; kk < 4; kk++) {
            const int grp = lane >> 3;
            const int c = kk * 2 + (grp & 1);
            const int rb = wn * 32 + ((grp >> 1) << 3) + (lane & 7);
            {
                uint32_t bf[4][2], bl[4][2];
#pragma unroll
                for (int np = 0; np < 2; np++) {
                    int r = rb + np * 16;
                    uint32_t ra = bb + r * 128 + ((c ^ (r & 7)) << 4);
                    uint32_t qv[4];
                    ldsm4(ra + AT_K1H, qv);
                    bf[np*2][0]=qv[0]; bf[np*2][1]=qv[1]; bf[np*2+1][0]=qv[2]; bf[np*2+1][1]=qv[3];
                    ldsm4(ra + AT_K1L, qv);
                    bl[np*2][0]=qv[0]; bl[np*2][1]=qv[1]; bl[np*2+1][0]=qv[2]; bl[np*2+1][1]=qv[3];
                }
#pragma unroll
                for (int nt = 0; nt < 4; nt++) {
                    mma16816(S1[nt], qfh[kk], bf[nt]);
                    mma16816(S1[nt], qfh[kk], bl[nt]);
                    mma16816(S1[nt], qfl[kk], bf[nt]);
                }
            }
            {
                uint32_t bf[4][2], bl[4][2];
#pragma unroll
                for (int np = 0; np < 2; np++) {
                    int r = rb + np * 16;
                    uint32_t ra = bb + r * 128 + ((c ^ (r & 7)) << 4);
                    uint32_t qv[4];
                    ldsm4(ra + AT_K2H, qv);
                    bf[np*2][0]=qv[0]; bf[np*2][1]=qv[1]; bf[np*2+1][0]=qv[2]; bf[np*2+1][1]=qv[3];
                    ldsm4(ra + AT_K2L, qv);
                    bl[np*2][0]=qv[0]; bl[np*2][1]=qv[1]; bl[np*2+1][0]=qv[2]; bl[np*2+1][1]=qv[3];
                }
#pragma unroll
                for (int nt = 0; nt < 4; nt++) {
                    mma16816(S2[nt], qfh[kk], bf[nt]);
                    mma16816(S2[nt], qfh[kk], bl[nt]);
                    mma16816(S2[nt], qfl[kk], bf[nt]);
                }
            }
        }

        // ---- weights: w = p1 e1 + p2 e2, packed into A-frags (registers) ----
        uint32_t wAh[2][4], wAl[2][4];
        {
            const float* k1p = (const float*)(smem + AT_N + (st & 1) * 512);
            const float* k2p = k1p + 64;
#pragma unroll
            for (int nt = 0; nt < 4; nt++) {
                const int cp0 = wn * 32 + nt * 8 + 2 * (lane & 3);
                const float k1a = k1p[cp0], k1b = k1p[cp0 + 1];
                const float k2a = k2p[cp0], k2b = k2p[cp0 + 1];
                float w00 = p1 * __expf(-0.0625f * (q2a + k1a - 2.0f * S1[nt][0]))
                          + p2 * __expf(-0.1875f * (q2a + k2a - 2.0f * S2[nt][0]));
                float w01 = p1 * __expf(-0.0625f * (q2a + k1b - 2.0f * S1[nt][1]))
                          + p2 * __expf(-0.1875f * (q2a + k2b - 2.0f * S2[nt][1]));
                float w10 = p1 * __expf(-0.0625f * (q2b + k1a - 2.0f * S1[nt][2]))
                          + p2 * __expf(-0.1875f * (q2b + k2a - 2.0f * S2[nt][2]));
                float w11 = p1 * __expf(-0.0625f * (q2b + k1b - 2.0f * S1[nt][3]))
                          + p2 * __expf(-0.1875f * (q2b + k2b - 2.0f * S2[nt][3]));
                den0 += w00 + w01;
                den1 += w10 + w11;
                uint32_t h0, l0, h1, l1;
                split2(w00, w01, h0, l0);
                split2(w10, w11, h1, l1);
                const int kk = nt >> 1;
                const int e = (nt & 1) * 2;
                wAh[kk][e]     = h0; wAl[kk][e]     = l0;
                wAh[kk][e + 1] = h1; wAl[kk][e + 1] = l1;
            }
        }

        // ---- AV: O(partial over s-half) += w @ V, all 64 cols ----
#pragma unroll
        for (int kk = 0; kk < 2; kk++) {
            uint32_t bvh[8][2], bvl[8][2];
            {
                int r = wn * 32 + kk * 16 + (lane & 15);
                uint32_t rowa = bb + AT_VH + r * 128;
                uint32_t rowb = bb + AT_VL + r * 128;
#pragma unroll
                for (int cb = 0; cb < 8; cb += 2) {
                    int g0 = cb + (lane >> 4);
                    uint32_t qv[4];
                    ldsm4t(rowa + ((g0 ^ (r & 7)) << 4), qv);
                    bvh[cb][0]=qv[0]; bvh[cb][1]=qv[1]; bvh[cb+1][0]=qv[2]; bvh[cb+1][1]=qv[3];
                    ldsm4t(rowb + ((g0 ^ (r & 7)) << 4), qv);
                    bvl[cb][0]=qv[0]; bvl[cb][1]=qv[1]; bvl[cb+1][0]=qv[2]; bvl[cb+1][1]=qv[3];
                }
            }
#pragma unroll
            for (int nt = 0; nt < 8; nt++) {
                mma16816(O[nt], wAh[kk], bvh[nt]);
                mma16816(O[nt], wAh[kk], bvl[nt]);
                mma16816(O[nt], wAl[kk], bvh[nt]);
            }
        }
    }
#undef LOADKV

    // ---- cross-warp reduction of O and den over the two s-halves ----
    den0 += __shfl_xor_sync(0xffffffffu, den0, 1);
    den0 += __shfl_xor_sync(0xffffffffu, den0, 2);
    den1 += __shfl_xor_sync(0xffffffffu, den1, 1);
    den1 += __shfl_xor_sync(0xffffffffu, den1, 2);

    float* dens = (float*)(smem + AT_DEN);
    float* ored = (float*)(smem + AT_ORED);   // pitch 34 floats, 64 rows
    const int r0 = wm + (lane >> 2);
    __syncthreads();
    if ((lane & 3) == 0) {
        dens[r0 * 2 + wn] = den0;
        dens[(r0 + 8) * 2 + wn] = den1;
    }
    // chunk 0: nt 0..3
    if (wn == 1) {
#pragma unroll
        for (int nt = 0; nt < 4; nt++) {
            const int c = nt * 8 + 2 * (lane & 3);
            *(float2*)&ored[r0 * 34 + c] = make_float2(O[nt][0], O[nt][1]);
            *(float2*)&ored[(r0 + 8) * 34 + c] = make_float2(O[nt][2], O[nt][3]);
        }
    }
    __syncthreads();
    float ia = 0.0f, ib = 0.0f;
    if (wn == 0) {
        ia = 1.0f / (dens[r0 * 2] + dens[r0 * 2 + 1] + 1e-6f);
        ib = 1.0f / (dens[(r0 + 8) * 2] + dens[(r0 + 8) * 2 + 1] + 1e-6f);
#pragma unroll
        for (int nt = 0; nt < 4; nt++) {
            const int c = nt * 8 + 2 * (lane & 3);
            float2 pa = *(const float2*)&ored[r0 * 34 + c];
            float2 pb = *(const float2*)&ored[(r0 + 8) * 34 + c];
            float o00 = (O[nt][0] + pa.x) * ia, o01 = (O[nt][1] + pa.y) * ia;
            float o10 = (O[nt][2] + pb.x) * ib, o11 = (O[nt][3] + pb.y) * ib;
            uint32_t h0, l0, h1, l1;
            split2(o00, o01, h0, l0);
            split2(o10, o11, h1, l1);
            size_t i0 = ((size_t)(q0 + r0) * B_SZ + b) * E_DIM + grow + c;
            size_t i1 = i0 + (size_t)8 * B_SZ * E_DIM;
            *(uint32_t*)&ao_h[i0] = h0; *(uint32_t*)&ao_l[i0] = l0;
            *(uint32_t*)&ao_h[i1] = h1; *(uint32_t*)&ao_l[i1] = l1;
        }
    }
    __syncthreads();
    // chunk 1: nt 4..7
    if (wn == 1) {
#pragma unroll
        for (int nt = 4; nt < 8; nt++) {
            const int c = (nt - 4) * 8 + 2 * (lane & 3);
            *(float2*)&ored[r0 * 34 + c] = make_float2(O[nt][0], O[nt][1]);
            *(float2*)&ored[(r0 + 8) * 34 + c] = make_float2(O[nt][2], O[nt][3]);
        }
    }
    __syncthreads();
    if (wn == 0) {
#pragma unroll
        for (int nt = 4; nt < 8; nt++) {
            const int c = (nt - 4) * 8 + 2 * (lane & 3);
            float2 pa = *(const float2*)&ored[r0 * 34 + c];
            float2 pb = *(const float2*)&ored[(r0 + 8) * 34 + c];
            float o00 = (O[nt][0] + pa.x) * ia, o01 = (O[nt][1] + pa.y) * ia;
            float o10 = (O[nt][2] + pb.x) * ib, o11 = (O[nt][3] + pb.y) * ib;
            uint32_t h0, l0, h1, l1;
            split2(o00, o01, h0, l0);
            split2(o10, o11, h1, l1);
            const int cg = nt * 8 + 2 * (lane & 3);
            size_t i0 = ((size_t)(q0 + r0) * B_SZ + b) * E_DIM + grow + cg;
            size_t i1 = i0 + (size_t)8 * B_SZ * E_DIM;
            *(uint32_t*)&ao_h[i0] = h0; *(uint32_t*)&ao_l[i0] = l0;
            *(uint32_t*)&ao_h[i1] = h1; *(uint32_t*)&ao_l[i1] = l1;
        }
    }
}

// ---------------------------------------------------------------------------
extern "C" void kernel_launch(void* const* d_in, const int* in_sizes, int n_in,
                              void* d_out, int out_size) {
    const float* query = (const float*)d_in[0];
    const float* key   = (const float*)d_in[1];
    const float* value = (const float*)d_in[2];
    const float* wq    = (const float*)d_in[3];
    const float* wk1   = (const float*)d_in[4];
    const float* wk2   = (const float*)d_in[5];
    const float* wv    = (const float*)d_in[6];
    const float* bias  = (const float*)d_in[7];
    const float* wo    = (const float*)d_in[8];
    const float* bo    = (const float*)d_in[9];
    const float* pi    = (const float*)d_in[10];
    float* out = (float*)d_out;

    cudaFuncSetAttribute(proj_kernel,
                         cudaFuncAttributeMaxDynamicSharedMemorySize, GEMM_SMEM);
    cudaFuncSetAttribute(out_kernel,
                         cudaFuncAttributeMaxDynamicSharedMemorySize, GEMM_SMEM);
    cudaFuncSetAttribute(attn_kernel,
                         cudaFuncAttributeMaxDynamicSharedMemorySize, ATTN_SMEM);

    dim3 gsplit(4096, 8);
    split_all<<<gsplit, 256>>>(query, key, value, wq, wk1, wk2, wv, wo);

    dim3 gproj(8, 32, 4);
    proj_kernel<<<gproj, 256, GEMM_SMEM>>>(bias);

    dim3 gnorm(256, 3);
    norm_kernel<<<gnorm, 256>>>();

    dim3 gattn(16, 64);
    attn_kernel<<<gattn, 256, ATTN_SMEM>>>(pi);

    dim3 gout(8, 32);
    out_kernel<<<gout, 256, GEMM_SMEM>>>(bo, out);
}

// round 12
// speedup vs baseline: 3.5210x; 1.0507x over previous
#include <cuda_runtime.h>
#include <cuda_bf16.h>
#include <math.h>
#include <cstdint>

#define E_DIM 1024
#define M_DIM 4096
#define H_NUM 16
#define HD 64
#define B_SZ 4
#define NELEM (M_DIM * E_DIM)
#define WSZ (E_DIM * E_DIM)

// exp(-c*d) = exp2(-c*log2e*d).  c1=1/16, c2=3/16.
#define NSC1 (-0.09016844005555976f)   // -c1*log2e
#define NSC2 (-0.27050532016667927f)   // -c2*log2e
#define SC1  (0.18033688011111952f)    // +2*c1*log2e
#define SC2  (0.54101064033335854f)    // +2*c2*log2e

// bf16 hi/lo split buffers (inputs to GEMMs)
__device__ __nv_bfloat16 in_q_h[NELEM], in_q_l[NELEM];
__device__ __nv_bfloat16 in_k_h[NELEM], in_k_l[NELEM];
__device__ __nv_bfloat16 in_v_h[NELEM], in_v_l[NELEM];
__device__ __nv_bfloat16 w_h[5 * WSZ],  w_l[5 * WSZ];

// proj outputs (bf16 hi/lo), attention output (bf16 hi/lo)
__device__ __nv_bfloat16 o_q_h[NELEM],  o_q_l[NELEM];
__device__ __nv_bfloat16 o_k1_h[NELEM], o_k1_l[NELEM];
__device__ __nv_bfloat16 o_k2_h[NELEM], o_k2_l[NELEM];
__device__ __nv_bfloat16 o_v_h[NELEM],  o_v_l[NELEM];
__device__ __nv_bfloat16 ao_h[NELEM],   ao_l[NELEM];

// norms: [bh*1024 + t].  n_q2 raw q^2; n_k1/n_k2 pre-scaled by NSC1/NSC2.
__device__ float n_q2[64 * 1024];
__device__ float n_k1[64 * 1024];
__device__ float n_k2[64 * 1024];

// ===========================================================================
// helpers
// ===========================================================================
__device__ __forceinline__ uint32_t smem_u32(const void* p) {
    uint32_t a;
    asm("{ .reg .u64 t; cvta.to.shared.u64 t, %1; cvt.u32.u64 %0, t; }"
        : "=r"(a) : "l"(p));
    return a;
}
__device__ __forceinline__ void cp_async16(uint32_t dst, const void* src) {
    asm volatile("cp.async.cg.shared.global [%0], [%1], 16;"
                 :: "r"(dst), "l"(src));
}
__device__ __forceinline__ void cp_commit() {
    asm volatile("cp.async.commit_group;" ::: "memory");
}
__device__ __forceinline__ void cp_wait1() {
    asm volatile("cp.async.wait_group 1;" ::: "memory");
}
__device__ __forceinline__ void cp_wait0() {
    asm volatile("cp.async.wait_group 0;" ::: "memory");
}
__device__ __forceinline__ void ldsm4(uint32_t addr, uint32_t* r) {
    asm volatile("ldmatrix.sync.aligned.m8n8.x4.shared.b16 {%0,%1,%2,%3}, [%4];"
                 : "=r"(r[0]), "=r"(r[1]), "=r"(r[2]), "=r"(r[3]) : "r"(addr));
}
__device__ __forceinline__ void ldsm4t(uint32_t addr, uint32_t* r) {
    asm volatile("ldmatrix.sync.aligned.m8n8.x4.trans.shared.b16 {%0,%1,%2,%3}, [%4];"
                 : "=r"(r[0]), "=r"(r[1]), "=r"(r[2]), "=r"(r[3]) : "r"(addr));
}
__device__ __forceinline__ void mma16816(float* d, const uint32_t* a,
                                         const uint32_t* b) {
    asm volatile(
        "mma.sync.aligned.m16n8k16.row.col.f32.bf16.bf16.f32 "
        "{%0,%1,%2,%3}, {%4,%5,%6,%7}, {%8,%9}, {%0,%1,%2,%3};"
        : "+f"(d[0]), "+f"(d[1]), "+f"(d[2]), "+f"(d[3])
        : "r"(a[0]), "r"(a[1]), "r"(a[2]), "r"(a[3]), "r"(b[0]), "r"(b[1]));
}
__device__ __forceinline__ float ex2f(float x) {
    float y;
    asm("ex2.approx.ftz.f32 %0, %1;" : "=f"(y) : "f"(x));
    return y;
}
__device__ __forceinline__ void split2(float x, float y, uint32_t& hi, uint32_t& lo) {
    __nv_bfloat162 h = __float22bfloat162_rn(make_float2(x, y));
    float2 f = __bfloat1622float2(h);
    __nv_bfloat162 l = __float22bfloat162_rn(make_float2(x - f.x, y - f.y));
    hi = *reinterpret_cast<uint32_t*>(&h);
    lo = *reinterpret_cast<uint32_t*>(&l);
}

// ===========================================================================
// fused fp32 -> bf16 hi/lo split for all 8 source tensors (one launch)
// ===========================================================================
extern "C" __global__ void __launch_bounds__(256)
split_all(const float* __restrict__ q, const float* __restrict__ k,
          const float* __restrict__ v, const float* __restrict__ wq,
          const float* __restrict__ wk1, const float* __restrict__ wk2,
          const float* __restrict__ wv, const float* __restrict__ wo) {
    const float* src;
    __nv_bfloat16 *hi, *lo;
    int n4;
    switch (blockIdx.y) {
        case 0: src = q;   hi = in_q_h; lo = in_q_l; n4 = NELEM / 4; break;
        case 1: src = k;   hi = in_k_h; lo = in_k_l; n4 = NELEM / 4; break;
        case 2: src = v;   hi = in_v_h; lo = in_v_l; n4 = NELEM / 4; break;
        case 3: src = wq;  hi = w_h + 0 * (size_t)WSZ; lo = w_l + 0 * (size_t)WSZ; n4 = WSZ / 4; break;
        case 4: src = wk1; hi = w_h + 1 * (size_t)WSZ; lo = w_l + 1 * (size_t)WSZ; n4 = WSZ / 4; break;
        case 5: src = wk2; hi = w_h + 2 * (size_t)WSZ; lo = w_l + 2 * (size_t)WSZ; n4 = WSZ / 4; break;
        case 6: src = wv;  hi = w_h + 3 * (size_t)WSZ; lo = w_l + 3 * (size_t)WSZ; n4 = WSZ / 4; break;
        default: src = wo; hi = w_h + 4 * (size_t)WSZ; lo = w_l + 4 * (size_t)WSZ; n4 = WSZ / 4; break;
    }
    int i = blockIdx.x * 256 + threadIdx.x;
    if (i >= n4) return;
    float4 val = ((const float4*)src)[i];
    uint32_t h0, l0, h1, l1;
    split2(val.x, val.y, h0, l0);
    split2(val.z, val.w, h1, l1);
    ((uint32_t*)hi)[i * 2]     = h0;
    ((uint32_t*)hi)[i * 2 + 1] = h1;
    ((uint32_t*)lo)[i * 2]     = l0;
    ((uint32_t*)lo)[i * 2 + 1] = l1;
}

// ===========================================================================
// mma.sync GEMM: C[M,N] = A[M,K] @ W[N,K]^T + bias  (bf16 hi/lo, fp32 acc)
// CTA 128x128, K chunk 32, 256 threads (8 warps, 4m x 2n, warp tile 32x64).
// Warp tile N=64 == one head width -> fused row-norm computation (nm != 0).
// nm: 0 = none, 1 = q (raw), 2 = k1 (scaled NSC1), 3 = k2 (scaled NSC2)
// ===========================================================================
#define GEMM_SMEM 65536

__device__ __forceinline__ void gemm_mma_body(
    const __nv_bfloat16* __restrict__ Ah, const __nv_bfloat16* __restrict__ Al,
    const __nv_bfloat16* __restrict__ Wh, const __nv_bfloat16* __restrict__ Wl,
    const float* __restrict__ bias, float* __restrict__ Cf,
    __nv_bfloat16* __restrict__ Ch, __nv_bfloat16* __restrict__ Cl,
    const int nm, float* __restrict__ Nout) {
    extern __shared__ char smem[];
    const uint32_t sbase = smem_u32(smem);
    const int tid = threadIdx.x;
    const int lane = tid & 31;
    const int wid = tid >> 5;
    const int bm = blockIdx.y * 128;
    const int bn = blockIdx.x * 128;
    const int wm = (wid & 3) * 32;
    const int wn = (wid >> 2) * 64;

    const int lr = tid >> 1;            // 0..127
    const int lg = (tid & 1) * 2;       // granule 0 or 2
    const size_t goffA = (size_t)(bm + lr) * E_DIM;
    const size_t goffW = (size_t)(bn + lr) * E_DIM;

    float acc[2][8][4];
#pragma unroll
    for (int mt = 0; mt < 2; mt++)
#pragma unroll
        for (int nt = 0; nt < 8; nt++)
#pragma unroll
            for (int e = 0; e < 4; e++) acc[mt][nt][e] = 0.0f;

#define LOAD_CHUNK(buf, kc) do {                                              \
    uint32_t dst0 = sbase + (buf) * 32768 + lr * 64;                          \
    _Pragma("unroll")                                                         \
    for (int j = 0; j < 2; j++) {                                             \
        int g = lg + j;                                                       \
        uint32_t d = dst0 + (((g) ^ ((lr >> 1) & 3)) << 4);                   \
        cp_async16(d,         Ah + goffA + (kc) + g * 8);                     \
        cp_async16(d + 8192,  Al + goffA + (kc) + g * 8);                     \
        cp_async16(d + 16384, Wh + goffW + (kc) + g * 8);                     \
        cp_async16(d + 24576, Wl + goffW + (kc) + g * 8);                     \
    }                                                                         \
} while (0)

    LOAD_CHUNK(0, 0);
    cp_commit();

    const int nk = E_DIM / 32;
    for (int kc = 0; kc < nk; kc++) {
        if (kc + 1 < nk) {
            LOAD_CHUNK((kc + 1) & 1, (kc + 1) * 32);
            cp_commit();
            cp_wait1();
        } else {
            cp_wait0();
        }
        __syncthreads();

        const uint32_t tb = sbase + (kc & 1) * 32768;
#pragma unroll
        for (int s = 0; s < 2; s++) {
            uint32_t a_h[2][4], a_l[2][4];
            const int ac = s * 2 + (lane >> 4);
#pragma unroll
            for (int mt = 0; mt < 2; mt++) {
                int r = wm + mt * 16 + (lane & 15);
                uint32_t ad = tb + r * 64 + ((ac ^ ((r >> 1) & 3)) << 4);
                ldsm4(ad, a_h[mt]);
                ldsm4(ad + 8192, a_l[mt]);
            }
            uint32_t b_h[8][2], b_l[8][2];
            const int grp = lane >> 3;
            const int bc = s * 2 + (grp & 1);
            const int br = wn + ((grp >> 1) << 3) + (lane & 7);
#pragma unroll
            for (int np = 0; np < 4; np++) {
                int r = br + np * 16;
                uint32_t bd = tb + 16384 + r * 64 + ((bc ^ ((r >> 1) & 3)) << 4);
                uint32_t qv[4];
                ldsm4(bd, qv);
                b_h[np * 2][0] = qv[0]; b_h[np * 2][1] = qv[1];
                b_h[np * 2 + 1][0] = qv[2]; b_h[np * 2 + 1][1] = qv[3];
                ldsm4(bd + 8192, qv);
                b_l[np * 2][0] = qv[0]; b_l[np * 2][1] = qv[1];
                b_l[np * 2 + 1][0] = qv[2]; b_l[np * 2 + 1][1] = qv[3];
            }
#pragma unroll
            for (int mt = 0; mt < 2; mt++)
#pragma unroll
                for (int nt = 0; nt < 8; nt++) {
                    mma16816(acc[mt][nt], a_h[mt], b_h[nt]);
                    mma16816(acc[mt][nt], a_h[mt], b_l[nt]);
                    mma16816(acc[mt][nt], a_l[mt], b_h[nt]);
                }
        }
        __syncthreads();
    }
#undef LOAD_CHUNK

    // epilogue (+ fused per-row squared-norm when nm != 0)
    const float nsc = (nm == 1) ? 1.0f : (nm == 2 ? NSC1 : NSC2);
#pragma unroll
    for (int mt = 0; mt < 2; mt++) {
        int r0 = bm + wm + mt * 16 + (lane >> 2);
        float ns0 = 0.0f, ns1 = 0.0f;
#pragma unroll
        for (int nt = 0; nt < 8; nt++) {
            int cg = bn + wn + nt * 8 + ((lane & 3) << 1);
            float2 bb = *(const float2*)&bias[cg];
            float v00 = acc[mt][nt][0] + bb.x, v01 = acc[mt][nt][1] + bb.y;
            float v10 = acc[mt][nt][2] + bb.x, v11 = acc[mt][nt][3] + bb.y;
            if (nm) {
                ns0 = fmaf(v00, v00, ns0); ns0 = fmaf(v01, v01, ns0);
                ns1 = fmaf(v10, v10, ns1); ns1 = fmaf(v11, v11, ns1);
            }
            if (Cf) {
                *(float2*)&Cf[(size_t)r0 * E_DIM + cg] = make_float2(v00, v01);
                *(float2*)&Cf[(size_t)(r0 + 8) * E_DIM + cg] = make_float2(v10, v11);
            } else {
                uint32_t h0, l0, h1, l1;
                split2(v00, v01, h0, l0);
                split2(v10, v11, h1, l1);
                *(uint32_t*)&Ch[(size_t)r0 * E_DIM + cg] = h0;
                *(uint32_t*)&Cl[(size_t)r0 * E_DIM + cg] = l0;
                *(uint32_t*)&Ch[(size_t)(r0 + 8) * E_DIM + cg] = h1;
                *(uint32_t*)&Cl[(size_t)(r0 + 8) * E_DIM + cg] = l1;
            }
        }
        if (nm) {
            ns0 += __shfl_xor_sync(0xffffffffu, ns0, 1);
            ns0 += __shfl_xor_sync(0xffffffffu, ns0, 2);
            ns1 += __shfl_xor_sync(0xffffffffu, ns1, 1);
            ns1 += __shfl_xor_sync(0xffffffffu, ns1, 2);
            if ((lane & 3) == 0) {
                const int hh = (bn + wn) >> 6;
                const int bb_ = r0 & 3;
                const size_t nb = (size_t)(bb_ * 16 + hh) * 1024;
                Nout[nb + (r0 >> 2)] = ns0 * nsc;
                Nout[nb + (r0 >> 2) + 2] = ns1 * nsc;
            }
        }
    }
}

// Fused 4-way projection: z=0:q z=1:k1 z=2:k2 z=3:v  -> bf16 hi/lo outputs
extern "C" __global__ void __launch_bounds__(256, 2)
proj_kernel(const float* __restrict__ bias) {
    int z = blockIdx.z;
    if (z == 0)
        gemm_mma_body(in_q_h, in_q_l, w_h, w_l, bias, nullptr,
                      o_q_h, o_q_l, 1, n_q2);
    else if (z == 1)
        gemm_mma_body(in_k_h, in_k_l, w_h + (size_t)WSZ, w_l + (size_t)WSZ,
                      bias + E_DIM, nullptr, o_k1_h, o_k1_l, 2, n_k1);
    else if (z == 2)
        gemm_mma_body(in_k_h, in_k_l, w_h + 2 * (size_t)WSZ, w_l + 2 * (size_t)WSZ,
                      bias + 2 * E_DIM, nullptr, o_k2_h, o_k2_l, 3, n_k2);
    else
        gemm_mma_body(in_v_h, in_v_l, w_h + 3 * (size_t)WSZ, w_l + 3 * (size_t)WSZ,
                      bias + 3 * E_DIM, nullptr, o_v_h, o_v_l, 0, nullptr);
}

extern "C" __global__ void __launch_bounds__(256, 2)
out_kernel(const float* __restrict__ bias, float* __restrict__ C) {
    gemm_mma_body(ao_h, ao_l, w_h + (size_t)4 * WSZ, w_l + (size_t)4 * WSZ,
                  bias, C, nullptr, nullptr, 0, nullptr);
}

// ===========================================================================
// Tensorized Gaussian-kernel attention; Q frags + q2 in registers.
// Block = (64 q rows, bh), 256 threads = 8 warps (4 m-strips x 2 s-halves).
// w = p1*exp2(SC1*S1 + qc1 + k1') + p2*exp2(SC2*S2 + qc2 + k2')
// ===========================================================================
#define AT_ORED 0
#define AT_DEN  8704
#define AT_N    9216
#define AT_BUF0 10240
#define AT_BUFSZ 49152
#define AT_K1H 0
#define AT_K1L 8192
#define AT_K2H 16384
#define AT_K2L 24576
#define AT_VH  32768
#define AT_VL  40960
#define ATTN_SMEM (AT_BUF0 + 2 * AT_BUFSZ)

extern "C" __global__ void __launch_bounds__(256, 2)
attn_kernel(const float* __restrict__ pi) {
    extern __shared__ char smem[];
    const uint32_t sb = smem_u32(smem);
    const int tid = threadIdx.x;
    const int lane = tid & 31;
    const int wid = tid >> 5;
    const int wm = (wid & 3) * 16;
    const int wn = wid >> 2;
    const int qt = blockIdx.x;
    const int bh = blockIdx.y;
    const int b = bh >> 4;
    const int h = bh & 15;
    const int q0 = qt * 64;

    const float p1 = fminf(fmaxf(fabsf(pi[h]), 1e-6f), 2.0f);
    const float p2 = fminf(fmaxf(fabsf(pi[H_NUM + h]), 1e-6f), 2.0f);

    const int lr = tid >> 2;
    const int lc = (tid & 3) * 2;
    const size_t grow = (size_t)h * HD;

#define LOADKV(buf, s0) do {                                                      \
    uint32_t bdst = sb + AT_BUF0 + (buf) * AT_BUFSZ;                              \
    size_t gsrc = ((size_t)((s0) + lr) * B_SZ + b) * E_DIM + grow;                \
    _Pragma("unroll")                                                             \
    for (int j = 0; j < 2; j++) {                                                 \
        int c = lc + j;                                                           \
        uint32_t d = bdst + lr * 128 + ((c ^ (lr & 7)) << 4);                     \
        cp_async16(d + AT_K1H, o_k1_h + gsrc + c * 8);                            \
        cp_async16(d + AT_K1L, o_k1_l + gsrc + c * 8);                            \
        cp_async16(d + AT_K2H, o_k2_h + gsrc + c * 8);                            \
        cp_async16(d + AT_K2L, o_k2_l + gsrc + c * 8);                            \
        cp_async16(d + AT_VH,  o_v_h  + gsrc + c * 8);                            \
        cp_async16(d + AT_VL,  o_v_l  + gsrc + c * 8);                            \
    }                                                                             \
    if (tid < 16)                                                                 \
        cp_async16(sb + AT_N + (buf) * 512 + tid * 16,                            \
                   n_k1 + (size_t)bh * 1024 + (s0) + tid * 4);                    \
    else if (tid < 32)                                                            \
        cp_async16(sb + AT_N + (buf) * 512 + 256 + (tid - 16) * 16,               \
                   n_k2 + (size_t)bh * 1024 + (s0) + (tid - 16) * 4);             \
} while (0)

    // ---- Q fragments + q2 straight into registers ----
    uint32_t qfh[4][4], qfl[4][4];
    {
        const int ra = q0 + wm + (lane >> 2);
        const size_t qa = ((size_t)ra * B_SZ + b) * E_DIM + grow;
        const size_t qb = qa + (size_t)8 * B_SZ * E_DIM;
#pragma unroll
        for (int kk = 0; kk < 4; kk++) {
            const int c0 = kk * 16 + 2 * (lane & 3);
            qfh[kk][0] = *(const uint32_t*)&o_q_h[qa + c0];
            qfh[kk][1] = *(const uint32_t*)&o_q_h[qb + c0];
            qfh[kk][2] = *(const uint32_t*)&o_q_h[qa + c0 + 8];
            qfh[kk][3] = *(const uint32_t*)&o_q_h[qb + c0 + 8];
            qfl[kk][0] = *(const uint32_t*)&o_q_l[qa + c0];
            qfl[kk][1] = *(const uint32_t*)&o_q_l[qb + c0];
            qfl[kk][2] = *(const uint32_t*)&o_q_l[qa + c0 + 8];
            qfl[kk][3] = *(const uint32_t*)&o_q_l[qb + c0 + 8];
        }
    }
    const float q2a = n_q2[(size_t)bh * 1024 + q0 + wm + (lane >> 2)];
    const float q2b = n_q2[(size_t)bh * 1024 + q0 + wm + (lane >> 2) + 8];
    const float qc1a = NSC1 * q2a, qc2a = NSC2 * q2a;
    const float qc1b = NSC1 * q2b, qc2b = NSC2 * q2b;

    LOADKV(0, 0);
    cp_commit();

    float O[8][4];
#pragma unroll
    for (int nt = 0; nt < 8; nt++)
#pragma unroll
        for (int e = 0; e < 4; e++) O[nt][e] = 0.0f;
    float den0 = 0.0f, den1 = 0.0f;

    for (int st = 0; st < 16; st++) {
        cp_wait0();
        __syncthreads();
        if (st < 15) { LOADKV((st + 1) & 1, (st + 1) * 64); cp_commit(); }

        const uint32_t bb = sb + AT_BUF0 + (st & 1) * AT_BUFSZ;

        float S1[4][4], S2[4][4];
#pragma unroll
        for (int nt = 0; nt < 4; nt++)
#pragma unroll
            for (int e = 0; e < 4; e++) { S1[nt][e] = 0.0f; S2[nt][e] = 0.0f; }

        // ---- QK over this warp's 32-key half (k1 then k2) ----
#pragma unroll
        for (int kk = 0; kk < 4; kk++) {
            const int grp = lane >> 3;
            const int c = kk * 2 + (grp & 1);
            const int rb = wn * 32 + ((grp >> 1) << 3) + (lane & 7);
            {
                uint32_t bf[4][2], bl[4][2];
#pragma unroll
                for (int np = 0; np < 2; np++) {
                    int r = rb + np * 16;
                    uint32_t ra = bb + r * 128 + ((c ^ (r & 7)) << 4);
                    uint32_t qv[4];
                    ldsm4(ra + AT_K1H, qv);
                    bf[np*2][0]=qv[0]; bf[np*2][1]=qv[1]; bf[np*2+1][0]=qv[2]; bf[np*2+1][1]=qv[3];
                    ldsm4(ra + AT_K1L, qv);
                    bl[np*2][0]=qv[0]; bl[np*2][1]=qv[1]; bl[np*2+1][0]=qv[2]; bl[np*2+1][1]=qv[3];
                }
#pragma unroll
                for (int nt = 0; nt < 4; nt++) {
                    mma16816(S1[nt], qfh[kk], bf[nt]);
                    mma16816(S1[nt], qfh[kk], bl[nt]);
                    mma16816(S1[nt], qfl[kk], bf[nt]);
                }
            }
            {
                uint32_t bf[4][2], bl[4][2];
#pragma unroll
                for (int np = 0; np < 2; np++) {
                    int r = rb + np * 16;
                    uint32_t ra = bb + r * 128 + ((c ^ (r & 7)) << 4);
                    uint32_t qv[4];
                    ldsm4(ra + AT_K2H, qv);
                    bf[np*2][0]=qv[0]; bf[np*2][1]=qv[1]; bf[np*2+1][0]=qv[2]; bf[np*2+1][1]=qv[3];
                    ldsm4(ra + AT_K2L, qv);
                    bl[np*2][0]=qv[0]; bl[np*2][1]=qv[1]; bl[np*2+1][0]=qv[2]; bl[np*2+1][1]=qv[3];
                }
#pragma unroll
                for (int nt = 0; nt < 4; nt++) {
                    mma16816(S2[nt], qfh[kk], bf[nt]);
                    mma16816(S2[nt], qfh[kk], bl[nt]);
                    mma16816(S2[nt], qfl[kk], bf[nt]);
                }
            }
        }

        // ---- weights: w = p1*ex2(SC1*S1 + t1) + p2*ex2(SC2*S2 + t2) ----
        uint32_t wAh[2][4], wAl[2][4];
        {
            const float* k1p = (const float*)(smem + AT_N + (st & 1) * 512);
            const float* k2p = k1p + 64;
#pragma unroll
            for (int nt = 0; nt < 4; nt++) {
                const int cp0 = wn * 32 + nt * 8 + 2 * (lane & 3);
                const float k1a = k1p[cp0], k1b = k1p[cp0 + 1];
                const float k2a = k2p[cp0], k2b = k2p[cp0 + 1];
                const float t1aa = qc1a + k1a, t1ab = qc1a + k1b;
                const float t1ba = qc1b + k1a, t1bb = qc1b + k1b;
                const float t2aa = qc2a + k2a, t2ab = qc2a + k2b;
                const float t2ba = qc2b + k2a, t2bb = qc2b + k2b;
                float w00 = fmaf(p1, ex2f(fmaf(SC1, S1[nt][0], t1aa)),
                                 p2 * ex2f(fmaf(SC2, S2[nt][0], t2aa)));
                float w01 = fmaf(p1, ex2f(fmaf(SC1, S1[nt][1], t1ab)),
                                 p2 * ex2f(fmaf(SC2, S2[nt][1], t2ab)));
                float w10 = fmaf(p1, ex2f(fmaf(SC1, S1[nt][2], t1ba)),
                                 p2 * ex2f(fmaf(SC2, S2[nt][2], t2ba)));
                float w11 = fmaf(p1, ex2f(fmaf(SC1, S1[nt][3], t1bb)),
                                 p2 * ex2f(fmaf(SC2, S2[nt][3], t2bb)));
                den0 += w00 + w01;
                den1 += w10 + w11;
                uint32_t h0, l0, h1, l1;
                split2(w00, w01, h0, l0);
                split2(w10, w11, h1, l1);
                const int kk = nt >> 1;
                const int e = (nt & 1) * 2;
                wAh[kk][e]     = h0; wAl[kk][e]     = l0;
                wAh[kk][e + 1] = h1; wAl[kk][e + 1] = l1;
            }
        }

        // ---- AV: O(partial over s-half) += w @ V, all 64 cols ----
#pragma unroll
        for (int kk = 0; kk < 2; kk++) {
            uint32_t bvh[8][2], bvl[8][2];
            {
                int r = wn * 32 + kk * 16 + (lane & 15);
                uint32_t rowa = bb + AT_VH + r * 128;
                uint32_t rowb = bb + AT_VL + r * 128;
#pragma unroll
                for (int cb = 0; cb < 8; cb += 2) {
                    int g0 = cb + (lane >> 4);
                    uint32_t qv[4];
                    ldsm4t(rowa + ((g0 ^ (r & 7)) << 4), qv);
                    bvh[cb][0]=qv[0]; bvh[cb][1]=qv[1]; bvh[cb+1][0]=qv[2]; bvh[cb+1][1]=qv[3];
                    ldsm4t(rowb + ((g0 ^ (r & 7)) << 4), qv);
                    bvl[cb][0]=qv[0]; bvl[cb][1]=qv[1]; bvl[cb+1][0]=qv[2]; bvl[cb+1][1]=qv[3];
                }
            }
#pragma unroll
            for (int nt = 0; nt < 8; nt++) {
                mma16816(O[nt], wAh[kk], bvh[nt]);
                mma16816(O[nt], wAh[kk], bvl[nt]);
                mma16816(O[nt], wAl[kk], bvh[nt]);
            }
        }
    }
#undef LOADKV

    // ---- cross-warp reduction of O and den over the two s-halves ----
    den0 += __shfl_xor_sync(0xffffffffu, den0, 1);
    den0 += __shfl_xor_sync(0xffffffffu, den0, 2);
    den1 += __shfl_xor_sync(0xffffffffu, den1, 1);
    den1 += __shfl_xor_sync(0xffffffffu, den1, 2);

    float* dens = (float*)(smem + AT_DEN);
    float* ored = (float*)(smem + AT_ORED);   // pitch 34 floats, 64 rows
    const int r0 = wm + (lane >> 2);
    __syncthreads();
    if ((lane & 3) == 0) {
        dens[r0 * 2 + wn] = den0;
        dens[(r0 + 8) * 2 + wn] = den1;
    }
    // chunk 0: nt 0..3
    if (wn == 1) {
#pragma unroll
        for (int nt = 0; nt < 4; nt++) {
            const int c = nt * 8 + 2 * (lane & 3);
            *(float2*)&ored[r0 * 34 + c] = make_float2(O[nt][0], O[nt][1]);
            *(float2*)&ored[(r0 + 8) * 34 + c] = make_float2(O[nt][2], O[nt][3]);
        }
    }
    __syncthreads();
    float ia = 0.0f, ib = 0.0f;
    if (wn == 0) {
        ia = 1.0f / (dens[r0 * 2] + dens[r0 * 2 + 1] + 1e-6f);
        ib = 1.0f / (dens[(r0 + 8) * 2] + dens[(r0 + 8) * 2 + 1] + 1e-6f);
#pragma unroll
        for (int nt = 0; nt < 4; nt++) {
            const int c = nt * 8 + 2 * (lane & 3);
            float2 pa = *(const float2*)&ored[r0 * 34 + c];
            float2 pb = *(const float2*)&ored[(r0 + 8) * 34 + c];
            float o00 = (O[nt][0] + pa.x) * ia, o01 = (O[nt][1] + pa.y) * ia;
            float o10 = (O[nt][2] + pb.x) * ib, o11 = (O[nt][3] + pb.y) * ib;
            uint32_t h0, l0, h1, l1;
            split2(o00, o01, h0, l0);
            split2(o10, o11, h1, l1);
            size_t i0 = ((size_t)(q0 + r0) * B_SZ + b) * E_DIM + grow + c;
            size_t i1 = i0 + (size_t)8 * B_SZ * E_DIM;
            *(uint32_t*)&ao_h[i0] = h0; *(uint32_t*)&ao_l[i0] = l0;
            *(uint32_t*)&ao_h[i1] = h1; *(uint32_t*)&ao_l[i1] = l1;
        }
    }
    __syncthreads();
    // chunk 1: nt 4..7
    if (wn == 1) {
#pragma unroll
        for (int nt = 4; nt < 8; nt++) {
            const int c = (nt - 4) * 8 + 2 * (lane & 3);
            *(float2*)&ored[r0 * 34 + c] = make_float2(O[nt][0], O[nt][1]);
            *(float2*)&ored[(r0 + 8) * 34 + c] = make_float2(O[nt][2], O[nt][3]);
        }
    }
    __syncthreads();
    if (wn == 0) {
#pragma unroll
        for (int nt = 4; nt < 8; nt++) {
            const int c = (nt - 4) * 8 + 2 * (lane & 3);
            float2 pa = *(const float2*)&ored[r0 * 34 + c];
            float2 pb = *(const float2*)&ored[(r0 + 8) * 34 + c];
            float o00 = (O[nt][0] + pa.x) * ia, o01 = (O[nt][1] + pa.y) * ia;
            float o10 = (O[nt][2] + pb.x) * ib, o11 = (O[nt][3] + pb.y) * ib;
            uint32_t h0, l0, h1, l1;
            split2(o00, o01, h0, l0);
            split2(o10, o11, h1, l1);
            const int cg = nt * 8 + 2 * (lane & 3);
            size_t i0 = ((size_t)(q0 + r0) * B_SZ + b) * E_DIM + grow + cg;
            size_t i1 = i0 + (size_t)8 * B_SZ * E_DIM;
            *(uint32_t*)&ao_h[i0] = h0; *(uint32_t*)&ao_l[i0] = l0;
            *(uint32_t*)&ao_h[i1] = h1; *(uint32_t*)&ao_l[i1] = l1;
        }
    }
}

// ---------------------------------------------------------------------------
extern "C" void kernel_launch(void* const* d_in, const int* in_sizes, int n_in,
                              void* d_out, int out_size) {
    const float* query = (const float*)d_in[0];
    const float* key   = (const float*)d_in[1];
    const float* value = (const float*)d_in[2];
    const float* wq    = (const float*)d_in[3];
    const float* wk1   = (const float*)d_in[4];
    const float* wk2   = (const float*)d_in[5];
    const float* wv    = (const float*)d_in[6];
    const float* bias  = (const float*)d_in[7];
    const float* wo    = (const float*)d_in[8];
    const float* bo    = (const float*)d_in[9];
    const float* pi    = (const float*)d_in[10];
    float* out = (float*)d_out;

    cudaFuncSetAttribute(proj_kernel,
                         cudaFuncAttributeMaxDynamicSharedMemorySize, GEMM_SMEM);
    cudaFuncSetAttribute(out_kernel,
                         cudaFuncAttributeMaxDynamicSharedMemorySize, GEMM_SMEM);
    cudaFuncSetAttribute(attn_kernel,
                         cudaFuncAttributeMaxDynamicSharedMemorySize, ATTN_SMEM);

    dim3 gsplit(4096, 8);
    split_all<<<gsplit, 256>>>(query, key, value, wq, wk1, wk2, wv, wo);

    dim3 gproj(8, 32, 4);
    proj_kernel<<<gproj, 256, GEMM_SMEM>>>(bias);

    dim3 gattn(16, 64);
    attn_kernel<<<gattn, 256, ATTN_SMEM>>>(pi);

    dim3 gout(8, 32);
    out_kernel<<<gout, 256, GEMM_SMEM>>>(bo, out);
}

// round 13
// speedup vs baseline: 3.5718x; 1.0144x over previous
#include <cuda_runtime.h>
#include <cuda_bf16.h>
#include <math.h>
#include <cstdint>

#define E_DIM 1024
#define M_DIM 4096
#define H_NUM 16
#define HD 64
#define B_SZ 4
#define NELEM (M_DIM * E_DIM)
#define WSZ (E_DIM * E_DIM)

// exp(-c*d) = exp2(-c*log2e*d).  c1=1/16, c2=3/16.
#define NSC1 (-0.09016844005555976f)   // -c1*log2e
#define NSC2 (-0.27050532016667927f)   // -c2*log2e
#define SC1  (0.18033688011111952f)    // +2*c1*log2e
#define SC2  (0.54101064033335854f)    // +2*c2*log2e

// bf16 hi/lo split buffers (inputs to GEMMs)
__device__ __nv_bfloat16 in_q_h[NELEM], in_q_l[NELEM];
__device__ __nv_bfloat16 in_k_h[NELEM], in_k_l[NELEM];
__device__ __nv_bfloat16 in_v_h[NELEM], in_v_l[NELEM];
__device__ __nv_bfloat16 w_h[5 * WSZ],  w_l[5 * WSZ];

// proj outputs (bf16 hi/lo), attention output (bf16 hi/lo)
__device__ __nv_bfloat16 o_q_h[NELEM],  o_q_l[NELEM];
__device__ __nv_bfloat16 o_k1_h[NELEM], o_k1_l[NELEM];
__device__ __nv_bfloat16 o_k2_h[NELEM], o_k2_l[NELEM];
__device__ __nv_bfloat16 o_v_h[NELEM],  o_v_l[NELEM];
__device__ __nv_bfloat16 ao_h[NELEM],   ao_l[NELEM];

// norms: [bh*1024 + t].  n_q2 raw q^2; n_k1/n_k2 pre-scaled by NSC1/NSC2.
__device__ float n_q2[64 * 1024];
__device__ float n_k1[64 * 1024];
__device__ float n_k2[64 * 1024];

// ===========================================================================
// helpers
// ===========================================================================
__device__ __forceinline__ uint32_t smem_u32(const void* p) {
    uint32_t a;
    asm("{ .reg .u64 t; cvta.to.shared.u64 t, %1; cvt.u32.u64 %0, t; }"
        : "=r"(a) : "l"(p));
    return a;
}
__device__ __forceinline__ void cp_async16(uint32_t dst, const void* src) {
    asm volatile("cp.async.cg.shared.global [%0], [%1], 16;"
                 :: "r"(dst), "l"(src));
}
__device__ __forceinline__ void cp_commit() {
    asm volatile("cp.async.commit_group;" ::: "memory");
}
__device__ __forceinline__ void cp_wait1() {
    asm volatile("cp.async.wait_group 1;" ::: "memory");
}
__device__ __forceinline__ void cp_wait0() {
    asm volatile("cp.async.wait_group 0;" ::: "memory");
}
__device__ __forceinline__ void ldsm4(uint32_t addr, uint32_t* r) {
    asm volatile("ldmatrix.sync.aligned.m8n8.x4.shared.b16 {%0,%1,%2,%3}, [%4];"
                 : "=r"(r[0]), "=r"(r[1]), "=r"(r[2]), "=r"(r[3]) : "r"(addr));
}
__device__ __forceinline__ void ldsm4t(uint32_t addr, uint32_t* r) {
    asm volatile("ldmatrix.sync.aligned.m8n8.x4.trans.shared.b16 {%0,%1,%2,%3}, [%4];"
                 : "=r"(r[0]), "=r"(r[1]), "=r"(r[2]), "=r"(r[3]) : "r"(addr));
}
__device__ __forceinline__ void mma16816(float* d, const uint32_t* a,
                                         const uint32_t* b) {
    asm volatile(
        "mma.sync.aligned.m16n8k16.row.col.f32.bf16.bf16.f32 "
        "{%0,%1,%2,%3}, {%4,%5,%6,%7}, {%8,%9}, {%0,%1,%2,%3};"
        : "+f"(d[0]), "+f"(d[1]), "+f"(d[2]), "+f"(d[3])
        : "r"(a[0]), "r"(a[1]), "r"(a[2]), "r"(a[3]), "r"(b[0]), "r"(b[1]));
}
__device__ __forceinline__ float ex2f(float x) {
    float y;
    asm("ex2.approx.ftz.f32 %0, %1;" : "=f"(y) : "f"(x));
    return y;
}
__device__ __forceinline__ void split2(float x, float y, uint32_t& hi, uint32_t& lo) {
    __nv_bfloat162 h = __float22bfloat162_rn(make_float2(x, y));
    float2 f = __bfloat1622float2(h);
    __nv_bfloat162 l = __float22bfloat162_rn(make_float2(x - f.x, y - f.y));
    hi = *reinterpret_cast<uint32_t*>(&h);
    lo = *reinterpret_cast<uint32_t*>(&l);
}

// ===========================================================================
// fused fp32 -> bf16 hi/lo split for all 8 source tensors (one launch)
// ===========================================================================
extern "C" __global__ void __launch_bounds__(256)
split_all(const float* __restrict__ q, const float* __restrict__ k,
          const float* __restrict__ v, const float* __restrict__ wq,
          const float* __restrict__ wk1, const float* __restrict__ wk2,
          const float* __restrict__ wv, const float* __restrict__ wo) {
    const float* src;
    __nv_bfloat16 *hi, *lo;
    int n4;
    switch (blockIdx.y) {
        case 0: src = q;   hi = in_q_h; lo = in_q_l; n4 = NELEM / 4; break;
        case 1: src = k;   hi = in_k_h; lo = in_k_l; n4 = NELEM / 4; break;
        case 2: src = v;   hi = in_v_h; lo = in_v_l; n4 = NELEM / 4; break;
        case 3: src = wq;  hi = w_h + 0 * (size_t)WSZ; lo = w_l + 0 * (size_t)WSZ; n4 = WSZ / 4; break;
        case 4: src = wk1; hi = w_h + 1 * (size_t)WSZ; lo = w_l + 1 * (size_t)WSZ; n4 = WSZ / 4; break;
        case 5: src = wk2; hi = w_h + 2 * (size_t)WSZ; lo = w_l + 2 * (size_t)WSZ; n4 = WSZ / 4; break;
        case 6: src = wv;  hi = w_h + 3 * (size_t)WSZ; lo = w_l + 3 * (size_t)WSZ; n4 = WSZ / 4; break;
        default: src = wo; hi = w_h + 4 * (size_t)WSZ; lo = w_l + 4 * (size_t)WSZ; n4 = WSZ / 4; break;
    }
    int i = blockIdx.x * 256 + threadIdx.x;
    if (i >= n4) return;
    float4 val = ((const float4*)src)[i];
    uint32_t h0, l0, h1, l1;
    split2(val.x, val.y, h0, l0);
    split2(val.z, val.w, h1, l1);
    ((uint32_t*)hi)[i * 2]     = h0;
    ((uint32_t*)hi)[i * 2 + 1] = h1;
    ((uint32_t*)lo)[i * 2]     = l0;
    ((uint32_t*)lo)[i * 2 + 1] = l1;
}

// ===========================================================================
// mma.sync GEMM: C[M,N] = A[M,K] @ W[N,K]^T + bias  (bf16 hi/lo, fp32 acc)
// CTA 128x128, K chunk 32, 256 threads (8 warps, 4m x 2n, warp tile 32x64).
// 3-stage cp.async pipeline, ONE barrier per K-chunk. smem 96KB, 2 CTA/SM.
// nm: 0 = none, 1 = q (raw), 2 = k1 (scaled NSC1), 3 = k2 (scaled NSC2)
// ===========================================================================
#define GEMM_SMEM 98304

__device__ __forceinline__ void gemm_mma_body(
    const __nv_bfloat16* __restrict__ Ah, const __nv_bfloat16* __restrict__ Al,
    const __nv_bfloat16* __restrict__ Wh, const __nv_bfloat16* __restrict__ Wl,
    const float* __restrict__ bias, float* __restrict__ Cf,
    __nv_bfloat16* __restrict__ Ch, __nv_bfloat16* __restrict__ Cl,
    const int nm, float* __restrict__ Nout) {
    extern __shared__ char smem[];
    const uint32_t sbase = smem_u32(smem);
    const int tid = threadIdx.x;
    const int lane = tid & 31;
    const int wid = tid >> 5;
    const int bm = blockIdx.y * 128;
    const int bn = blockIdx.x * 128;
    const int wm = (wid & 3) * 32;
    const int wn = (wid >> 2) * 64;

    const int lr = tid >> 1;            // 0..127
    const int lg = (tid & 1) * 2;       // granule 0 or 2
    const size_t goffA = (size_t)(bm + lr) * E_DIM;
    const size_t goffW = (size_t)(bn + lr) * E_DIM;

    float acc[2][8][4];
#pragma unroll
    for (int mt = 0; mt < 2; mt++)
#pragma unroll
        for (int nt = 0; nt < 8; nt++)
#pragma unroll
            for (int e = 0; e < 4; e++) acc[mt][nt][e] = 0.0f;

#define LOAD_CHUNK(buf, kc) do {                                              \
    uint32_t dst0 = sbase + (buf) * 32768 + lr * 64;                          \
    _Pragma("unroll")                                                         \
    for (int j = 0; j < 2; j++) {                                             \
        int g = lg + j;                                                       \
        uint32_t d = dst0 + (((g) ^ ((lr >> 1) & 3)) << 4);                   \
        cp_async16(d,         Ah + goffA + (kc) + g * 8);                     \
        cp_async16(d + 8192,  Al + goffA + (kc) + g * 8);                     \
        cp_async16(d + 16384, Wh + goffW + (kc) + g * 8);                     \
        cp_async16(d + 24576, Wl + goffW + (kc) + g * 8);                     \
    }                                                                         \
} while (0)

    LOAD_CHUNK(0, 0);
    cp_commit();
    LOAD_CHUNK(1, 32);
    cp_commit();

    const int nk = E_DIM / 32;
    int stage = 0;
    for (int kc = 0; kc < nk; kc++) {
        cp_wait1();               // oldest outstanding group (this stage) done
        __syncthreads();
        if (kc + 2 < nk) {
            int ns = stage + 2; if (ns >= 3) ns -= 3;
            LOAD_CHUNK(ns, (kc + 2) * 32);
            cp_commit();
        }

        const uint32_t tb = sbase + stage * 32768;
#pragma unroll
        for (int s = 0; s < 2; s++) {
            uint32_t a_h[2][4], a_l[2][4];
            const int ac = s * 2 + (lane >> 4);
#pragma unroll
            for (int mt = 0; mt < 2; mt++) {
                int r = wm + mt * 16 + (lane & 15);
                uint32_t ad = tb + r * 64 + ((ac ^ ((r >> 1) & 3)) << 4);
                ldsm4(ad, a_h[mt]);
                ldsm4(ad + 8192, a_l[mt]);
            }
            uint32_t b_h[8][2], b_l[8][2];
            const int grp = lane >> 3;
            const int bc = s * 2 + (grp & 1);
            const int br = wn + ((grp >> 1) << 3) + (lane & 7);
#pragma unroll
            for (int np = 0; np < 4; np++) {
                int r = br + np * 16;
                uint32_t bd = tb + 16384 + r * 64 + ((bc ^ ((r >> 1) & 3)) << 4);
                uint32_t qv[4];
                ldsm4(bd, qv);
                b_h[np * 2][0] = qv[0]; b_h[np * 2][1] = qv[1];
                b_h[np * 2 + 1][0] = qv[2]; b_h[np * 2 + 1][1] = qv[3];
                ldsm4(bd + 8192, qv);
                b_l[np * 2][0] = qv[0]; b_l[np * 2][1] = qv[1];
                b_l[np * 2 + 1][0] = qv[2]; b_l[np * 2 + 1][1] = qv[3];
            }
#pragma unroll
            for (int mt = 0; mt < 2; mt++)
#pragma unroll
                for (int nt = 0; nt < 8; nt++) {
                    mma16816(acc[mt][nt], a_h[mt], b_h[nt]);
                    mma16816(acc[mt][nt], a_h[mt], b_l[nt]);
                    mma16816(acc[mt][nt], a_l[mt], b_h[nt]);
                }
        }
        if (++stage >= 3) stage = 0;
    }
#undef LOAD_CHUNK

    // epilogue (+ fused per-row squared-norm when nm != 0)
    const float nsc = (nm == 1) ? 1.0f : (nm == 2 ? NSC1 : NSC2);
#pragma unroll
    for (int mt = 0; mt < 2; mt++) {
        int r0 = bm + wm + mt * 16 + (lane >> 2);
        float ns0 = 0.0f, ns1 = 0.0f;
#pragma unroll
        for (int nt = 0; nt < 8; nt++) {
            int cg = bn + wn + nt * 8 + ((lane & 3) << 1);
            float2 bb = *(const float2*)&bias[cg];
            float v00 = acc[mt][nt][0] + bb.x, v01 = acc[mt][nt][1] + bb.y;
            float v10 = acc[mt][nt][2] + bb.x, v11 = acc[mt][nt][3] + bb.y;
            if (nm) {
                ns0 = fmaf(v00, v00, ns0); ns0 = fmaf(v01, v01, ns0);
                ns1 = fmaf(v10, v10, ns1); ns1 = fmaf(v11, v11, ns1);
            }
            if (Cf) {
                *(float2*)&Cf[(size_t)r0 * E_DIM + cg] = make_float2(v00, v01);
                *(float2*)&Cf[(size_t)(r0 + 8) * E_DIM + cg] = make_float2(v10, v11);
            } else {
                uint32_t h0, l0, h1, l1;
                split2(v00, v01, h0, l0);
                split2(v10, v11, h1, l1);
                *(uint32_t*)&Ch[(size_t)r0 * E_DIM + cg] = h0;
                *(uint32_t*)&Cl[(size_t)r0 * E_DIM + cg] = l0;
                *(uint32_t*)&Ch[(size_t)(r0 + 8) * E_DIM + cg] = h1;
                *(uint32_t*)&Cl[(size_t)(r0 + 8) * E_DIM + cg] = l1;
            }
        }
        if (nm) {
            ns0 += __shfl_xor_sync(0xffffffffu, ns0, 1);
            ns0 += __shfl_xor_sync(0xffffffffu, ns0, 2);
            ns1 += __shfl_xor_sync(0xffffffffu, ns1, 1);
            ns1 += __shfl_xor_sync(0xffffffffu, ns1, 2);
            if ((lane & 3) == 0) {
                const int hh = (bn + wn) >> 6;
                const int bb_ = r0 & 3;
                const size_t nb = (size_t)(bb_ * 16 + hh) * 1024;
                Nout[nb + (r0 >> 2)] = ns0 * nsc;
                Nout[nb + (r0 >> 2) + 2] = ns1 * nsc;
            }
        }
    }
}

// Fused 4-way projection: z=0:q z=1:k1 z=2:k2 z=3:v  -> bf16 hi/lo outputs
extern "C" __global__ void __launch_bounds__(256, 2)
proj_kernel(const float* __restrict__ bias) {
    int z = blockIdx.z;
    if (z == 0)
        gemm_mma_body(in_q_h, in_q_l, w_h, w_l, bias, nullptr,
                      o_q_h, o_q_l, 1, n_q2);
    else if (z == 1)
        gemm_mma_body(in_k_h, in_k_l, w_h + (size_t)WSZ, w_l + (size_t)WSZ,
                      bias + E_DIM, nullptr, o_k1_h, o_k1_l, 2, n_k1);
    else if (z == 2)
        gemm_mma_body(in_k_h, in_k_l, w_h + 2 * (size_t)WSZ, w_l + 2 * (size_t)WSZ,
                      bias + 2 * E_DIM, nullptr, o_k2_h, o_k2_l, 3, n_k2);
    else
        gemm_mma_body(in_v_h, in_v_l, w_h + 3 * (size_t)WSZ, w_l + 3 * (size_t)WSZ,
                      bias + 3 * E_DIM, nullptr, o_v_h, o_v_l, 0, nullptr);
}

extern "C" __global__ void __launch_bounds__(256, 2)
out_kernel(const float* __restrict__ bias, float* __restrict__ C) {
    gemm_mma_body(ao_h, ao_l, w_h + (size_t)4 * WSZ, w_l + (size_t)4 * WSZ,
                  bias, C, nullptr, nullptr, 0, nullptr);
}

// ===========================================================================
// Tensorized Gaussian-kernel attention; Q frags + q2 in registers.
// Block = (64 q rows, bh), 256 threads = 8 warps (4 m-strips x 2 s-halves).
// w = p1*exp2(SC1*S1 + qc1 + k1') + p2*exp2(SC2*S2 + qc2 + k2')
// ===========================================================================
#define AT_ORED 0
#define AT_DEN  8704
#define AT_N    9216
#define AT_BUF0 10240
#define AT_BUFSZ 49152
#define AT_K1H 0
#define AT_K1L 8192
#define AT_K2H 16384
#define AT_K2L 24576
#define AT_VH  32768
#define AT_VL  40960
#define ATTN_SMEM (AT_BUF0 + 2 * AT_BUFSZ)

extern "C" __global__ void __launch_bounds__(256, 2)
attn_kernel(const float* __restrict__ pi) {
    extern __shared__ char smem[];
    const uint32_t sb = smem_u32(smem);
    const int tid = threadIdx.x;
    const int lane = tid & 31;
    const int wid = tid >> 5;
    const int wm = (wid & 3) * 16;
    const int wn = wid >> 2;
    const int qt = blockIdx.x;
    const int bh = blockIdx.y;
    const int b = bh >> 4;
    const int h = bh & 15;
    const int q0 = qt * 64;

    const float p1 = fminf(fmaxf(fabsf(pi[h]), 1e-6f), 2.0f);
    const float p2 = fminf(fmaxf(fabsf(pi[H_NUM + h]), 1e-6f), 2.0f);

    const int lr = tid >> 2;
    const int lc = (tid & 3) * 2;
    const size_t grow = (size_t)h * HD;

#define LOADKV(buf, s0) do {                                                      \
    uint32_t bdst = sb + AT_BUF0 + (buf) * AT_BUFSZ;                              \
    size_t gsrc = ((size_t)((s0) + lr) * B_SZ + b) * E_DIM + grow;                \
    _Pragma("unroll")                                                             \
    for (int j = 0; j < 2; j++) {                                                 \
        int c = lc + j;                                                           \
        uint32_t d = bdst + lr * 128 + ((c ^ (lr & 7)) << 4);                     \
        cp_async16(d + AT_K1H, o_k1_h + gsrc + c * 8);                            \
        cp_async16(d + AT_K1L, o_k1_l + gsrc + c * 8);                            \
        cp_async16(d + AT_K2H, o_k2_h + gsrc + c * 8);                            \
        cp_async16(d + AT_K2L, o_k2_l + gsrc + c * 8);                            \
        cp_async16(d + AT_VH,  o_v_h  + gsrc + c * 8);                            \
        cp_async16(d + AT_VL,  o_v_l  + gsrc + c * 8);                            \
    }                                                                             \
    if (tid < 16)                                                                 \
        cp_async16(sb + AT_N + (buf) * 512 + tid * 16,                            \
                   n_k1 + (size_t)bh * 1024 + (s0) + tid * 4);                    \
    else if (tid < 32)                                                            \
        cp_async16(sb + AT_N + (buf) * 512 + 256 + (tid - 16) * 16,               \
                   n_k2 + (size_t)bh * 1024 + (s0) + (tid - 16) * 4);             \
} while (0)

    // ---- Q fragments + q2 straight into registers ----
    uint32_t qfh[4][4], qfl[4][4];
    {
        const int ra = q0 + wm + (lane >> 2);
        const size_t qa = ((size_t)ra * B_SZ + b) * E_DIM + grow;
        const size_t qb = qa + (size_t)8 * B_SZ * E_DIM;
#pragma unroll
        for (int kk = 0; kk < 4; kk++) {
            const int c0 = kk * 16 + 2 * (lane & 3);
            qfh[kk][0] = *(const uint32_t*)&o_q_h[qa + c0];
            qfh[kk][1] = *(const uint32_t*)&o_q_h[qb + c0];
            qfh[kk][2] = *(const uint32_t*)&o_q_h[qa + c0 + 8];
            qfh[kk][3] = *(const uint32_t*)&o_q_h[qb + c0 + 8];
            qfl[kk][0] = *(const uint32_t*)&o_q_l[qa + c0];
            qfl[kk][1] = *(const uint32_t*)&o_q_l[qb + c0];
            qfl[kk][2] = *(const uint32_t*)&o_q_l[qa + c0 + 8];
            qfl[kk][3] = *(const uint32_t*)&o_q_l[qb + c0 + 8];
        }
    }
    const float q2a = n_q2[(size_t)bh * 1024 + q0 + wm + (lane >> 2)];
    const float q2b = n_q2[(size_t)bh * 1024 + q0 + wm + (lane >> 2) + 8];
    const float qc1a = NSC1 * q2a, qc2a = NSC2 * q2a;
    const float qc1b = NSC1 * q2b, qc2b = NSC2 * q2b;

    LOADKV(0, 0);
    cp_commit();

    float O[8][4];
#pragma unroll
    for (int nt = 0; nt < 8; nt++)
#pragma unroll
        for (int e = 0; e < 4; e++) O[nt][e] = 0.0f;
    float den0 = 0.0f, den1 = 0.0f;

    for (int st = 0; st < 16; st++) {
        cp_wait0();
        __syncthreads();
        if (st < 15) { LOADKV((st + 1) & 1, (st + 1) * 64); cp_commit(); }

        const uint32_t bb = sb + AT_BUF0 + (st & 1) * AT_BUFSZ;

        float S1[4][4], S2[4][4];
#pragma unroll
        for (int nt = 0; nt < 4; nt++)
#pragma unroll
            for (int e = 0; e < 4; e++) { S1[nt][e] = 0.0f; S2[nt][e] = 0.0f; }

        // ---- QK over this warp's 32-key half (k1 then k2) ----
#pragma unroll
        for (int kk = 0; kk < 4; kk++) {
            const int grp = lane >> 3;
            const int c = kk * 2 + (grp & 1);
            const int rb = wn * 32 + ((grp >> 1) << 3) + (lane & 7);
            {
                uint32_t bf[4][2], bl[4][2];
#pragma unroll
                for (int np = 0; np < 2; np++) {
                    int r = rb + np * 16;
                    uint32_t ra = bb + r * 128 + ((c ^ (r & 7)) << 4);
                    uint32_t qv[4];
                    ldsm4(ra + AT_K1H, qv);
                    bf[np*2][0]=qv[0]; bf[np*2][1]=qv[1]; bf[np*2+1][0]=qv[2]; bf[np*2+1][1]=qv[3];
                    ldsm4(ra + AT_K1L, qv);
                    bl[np*2][0]=qv[0]; bl[np*2][1]=qv[1]; bl[np*2+1][0]=qv[2]; bl[np*2+1][1]=qv[3];
                }
#pragma unroll
                for (int nt = 0; nt < 4; nt++) {
                    mma16816(S1[nt], qfh[kk], bf[nt]);
                    mma16816(S1[nt], qfh[kk], bl[nt]);
                    mma16816(S1[nt], qfl[kk], bf[nt]);
                }
            }
            {
                uint32_t bf[4][2], bl[4][2];
#pragma unroll
                for (int np = 0; np < 2; np++) {
                    int r = rb + np * 16;
                    uint32_t ra = bb + r * 128 + ((c ^ (r & 7)) << 4);
                    uint32_t qv[4];
                    ldsm4(ra + AT_K2H, qv);
                    bf[np*2][0]=qv[0]; bf[np*2][1]=qv[1]; bf[np*2+1][0]=qv[2]; bf[np*2+1][1]=qv[3];
                    ldsm4(ra + AT_K2L, qv);
                    bl[np*2][0]=qv[0]; bl[np*2][1]=qv[1]; bl[np*2+1][0]=qv[2]; bl[np*2+1][1]=qv[3];
                }
#pragma unroll
                for (int nt = 0; nt < 4; nt++) {
                    mma16816(S2[nt], qfh[kk], bf[nt]);
                    mma16816(S2[nt], qfh[kk], bl[nt]);
                    mma16816(S2[nt], qfl[kk], bf[nt]);
                }
            }
        }

        // ---- weights: w = p1*ex2(SC1*S1 + t1) + p2*ex2(SC2*S2 + t2) ----
        uint32_t wAh[2][4], wAl[2][4];
        {
            const float* k1p = (const float*)(smem + AT_N + (st & 1) * 512);
            const float* k2p = k1p + 64;
#pragma unroll
            for (int nt = 0; nt < 4; nt++) {
                const int cp0 = wn * 32 + nt * 8 + 2 * (lane & 3);
                const float k1a = k1p[cp0], k1b = k1p[cp0 + 1];
                const float k2a = k2p[cp0], k2b = k2p[cp0 + 1];
                const float t1aa = qc1a + k1a, t1ab = qc1a + k1b;
                const float t1ba = qc1b + k1a, t1bb = qc1b + k1b;
                const float t2aa = qc2a + k2a, t2ab = qc2a + k2b;
                const float t2ba = qc2b + k2a, t2bb = qc2b + k2b;
                float w00 = fmaf(p1, ex2f(fmaf(SC1, S1[nt][0], t1aa)),
                                 p2 * ex2f(fmaf(SC2, S2[nt][0], t2aa)));
                float w01 = fmaf(p1, ex2f(fmaf(SC1, S1[nt][1], t1ab)),
                                 p2 * ex2f(fmaf(SC2, S2[nt][1], t2ab)));
                float w10 = fmaf(p1, ex2f(fmaf(SC1, S1[nt][2], t1ba)),
                                 p2 * ex2f(fmaf(SC2, S2[nt][2], t2ba)));
                float w11 = fmaf(p1, ex2f(fmaf(SC1, S1[nt][3], t1bb)),
                                 p2 * ex2f(fmaf(SC2, S2[nt][3], t2bb)));
                den0 += w00 + w01;
                den1 += w10 + w11;
                uint32_t h0, l0, h1, l1;
                split2(w00, w01, h0, l0);
                split2(w10, w11, h1, l1);
                const int kk = nt >> 1;
                const int e = (nt & 1) * 2;
                wAh[kk][e]     = h0; wAl[kk][e]     = l0;
                wAh[kk][e + 1] = h1; wAl[kk][e + 1] = l1;
            }
        }

        // ---- AV: O(partial over s-half) += w @ V, all 64 cols ----
#pragma unroll
        for (int kk = 0; kk < 2; kk++) {
            uint32_t bvh[8][2], bvl[8][2];
            {
                int r = wn * 32 + kk * 16 + (lane & 15);
                uint32_t rowa = bb + AT_VH + r * 128;
                uint32_t rowb = bb + AT_VL + r * 128;
#pragma unroll
                for (int cb = 0; cb < 8; cb += 2) {
                    int g0 = cb + (lane >> 4);
                    uint32_t qv[4];
                    ldsm4t(rowa + ((g0 ^ (r & 7)) << 4), qv);
                    bvh[cb][0]=qv[0]; bvh[cb][1]=qv[1]; bvh[cb+1][0]=qv[2]; bvh[cb+1][1]=qv[3];
                    ldsm4t(rowb + ((g0 ^ (r & 7)) << 4), qv);
                    bvl[cb][0]=qv[0]; bvl[cb][1]=qv[1]; bvl[cb+1][0]=qv[2]; bvl[cb+1][1]=qv[3];
                }
            }
#pragma unroll
            for (int nt = 0; nt < 8; nt++) {
                mma16816(O[nt], wAh[kk], bvh[nt]);
                mma16816(O[nt], wAh[kk], bvl[nt]);
                mma16816(O[nt], wAl[kk], bvh[nt]);
            }
        }
    }
#undef LOADKV

    // ---- cross-warp reduction of O and den over the two s-halves ----
    den0 += __shfl_xor_sync(0xffffffffu, den0, 1);
    den0 += __shfl_xor_sync(0xffffffffu, den0, 2);
    den1 += __shfl_xor_sync(0xffffffffu, den1, 1);
    den1 += __shfl_xor_sync(0xffffffffu, den1, 2);

    float* dens = (float*)(smem + AT_DEN);
    float* ored = (float*)(smem + AT_ORED);   // pitch 34 floats, 64 rows
    const int r0 = wm + (lane >> 2);
    __syncthreads();
    if ((lane & 3) == 0) {
        dens[r0 * 2 + wn] = den0;
        dens[(r0 + 8) * 2 + wn] = den1;
    }
    // chunk 0: nt 0..3
    if (wn == 1) {
#pragma unroll
        for (int nt = 0; nt < 4; nt++) {
            const int c = nt * 8 + 2 * (lane & 3);
            *(float2*)&ored[r0 * 34 + c] = make_float2(O[nt][0], O[nt][1]);
            *(float2*)&ored[(r0 + 8) * 34 + c] = make_float2(O[nt][2], O[nt][3]);
        }
    }
    __syncthreads();
    float ia = 0.0f, ib = 0.0f;
    if (wn == 0) {
        ia = 1.0f / (dens[r0 * 2] + dens[r0 * 2 + 1] + 1e-6f);
        ib = 1.0f / (dens[(r0 + 8) * 2] + dens[(r0 + 8) * 2 + 1] + 1e-6f);
#pragma unroll
        for (int nt = 0; nt < 4; nt++) {
            const int c = nt * 8 + 2 * (lane & 3);
            float2 pa = *(const float2*)&ored[r0 * 34 + c];
            float2 pb = *(const float2*)&ored[(r0 + 8) * 34 + c];
            float o00 = (O[nt][0] + pa.x) * ia, o01 = (O[nt][1] + pa.y) * ia;
            float o10 = (O[nt][2] + pb.x) * ib, o11 = (O[nt][3] + pb.y) * ib;
            uint32_t h0, l0, h1, l1;
            split2(o00, o01, h0, l0);
            split2(o10, o11, h1, l1);
            size_t i0 = ((size_t)(q0 + r0) * B_SZ + b) * E_DIM + grow + c;
            size_t i1 = i0 + (size_t)8 * B_SZ * E_DIM;
            *(uint32_t*)&ao_h[i0] = h0; *(uint32_t*)&ao_l[i0] = l0;
            *(uint32_t*)&ao_h[i1] = h1; *(uint32_t*)&ao_l[i1] = l1;
        }
    }
    __syncthreads();
    // chunk 1: nt 4..7
    if (wn == 1) {
#pragma unroll
        for (int nt = 4; nt < 8; nt++) {
            const int c = (nt - 4) * 8 + 2 * (lane & 3);
            *(float2*)&ored[r0 * 34 + c] = make_float2(O[nt][0], O[nt][1]);
            *(float2*)&ored[(r0 + 8) * 34 + c] = make_float2(O[nt][2], O[nt][3]);
        }
    }
    __syncthreads();
    if (wn == 0) {
#pragma unroll
        for (int nt = 4; nt < 8; nt++) {
            const int c = (nt - 4) * 8 + 2 * (lane & 3);
            float2 pa = *(const float2*)&ored[r0 * 34 + c];
            float2 pb = *(const float2*)&ored[(r0 + 8) * 34 + c];
            float o00 = (O[nt][0] + pa.x) * ia, o01 = (O[nt][1] + pa.y) * ia;
            float o10 = (O[nt][2] + pb.x) * ib, o11 = (O[nt][3] + pb.y) * ib;
            uint32_t h0, l0, h1, l1;
            split2(o00, o01, h0, l0);
            split2(o10, o11, h1, l1);
            const int cg = nt * 8 + 2 * (lane & 3);
            size_t i0 = ((size_t)(q0 + r0) * B_SZ + b) * E_DIM + grow + cg;
            size_t i1 = i0 + (size_t)8 * B_SZ * E_DIM;
            *(uint32_t*)&ao_h[i0] = h0; *(uint32_t*)&ao_l[i0] = l0;
            *(uint32_t*)&ao_h[i1] = h1; *(uint32_t*)&ao_l[i1] = l1;
        }
    }
}

// ---------------------------------------------------------------------------
extern "C" void kernel_launch(void* const* d_in, const int* in_sizes, int n_in,
                              void* d_out, int out_size) {
    const float* query = (const float*)d_in[0];
    const float* key   = (const float*)d_in[1];
    const float* value = (const float*)d_in[2];
    const float* wq    = (const float*)d_in[3];
    const float* wk1   = (const float*)d_in[4];
    const float* wk2   = (const float*)d_in[5];
    const float* wv    = (const float*)d_in[6];
    const float* bias  = (const float*)d_in[7];
    const float* wo    = (const float*)d_in[8];
    const float* bo    = (const float*)d_in[9];
    const float* pi    = (const float*)d_in[10];
    float* out = (float*)d_out;

    cudaFuncSetAttribute(proj_kernel,
                         cudaFuncAttributeMaxDynamicSharedMemorySize, GEMM_SMEM);
    cudaFuncSetAttribute(out_kernel,
                         cudaFuncAttributeMaxDynamicSharedMemorySize, GEMM_SMEM);
    cudaFuncSetAttribute(attn_kernel,
                         cudaFuncAttributeMaxDynamicSharedMemorySize, ATTN_SMEM);

    dim3 gsplit(4096, 8);
    split_all<<<gsplit, 256>>>(query, key, value, wq, wk1, wk2, wv, wo);

    dim3 gproj(8, 32, 4);
    proj_kernel<<<gproj, 256, GEMM_SMEM>>>(bias);

    dim3 gattn(16, 64);
    attn_kernel<<<gattn, 256, ATTN_SMEM>>>(pi);

    dim3 gout(8, 32);
    out_kernel<<<gout, 256, GEMM_SMEM>>>(bo, out);
}